// round 1
// baseline (speedup 1.0000x reference)
#include <cuda_runtime.h>
#include <cuda_bf16.h>
#include <stdint.h>

#define NB   8
#define MM   2048
#define DIN  64
#define DH   128
#define NODES (NB*MM)

// scratch for gx as split bf16 (hi + lo)  — __device__ globals (no allocation)
__device__ __nv_bfloat16 g_ghi[NODES * DH];
__device__ __nv_bfloat16 g_glo[NODES * DH];

// ---------------------------------------------------------------------------
// Stage 1: per-node MLPs. self_dyn -> d_out, gx -> g_ghi/g_glo (split bf16).
// Block: 256 threads, 64 nodes (8 threads per node-pair: nd and nd+32).
// All weights staged in smem; g_w1 collapsed: w1g[k][j] = g_w1[k][j]+g_w1[k+64][j].
// ---------------------------------------------------------------------------
__global__ __launch_bounds__(256) void stage1_kernel(
    const float* __restrict__ x,
    const float* __restrict__ fw1, const float* __restrict__ fb1,
    const float* __restrict__ fw2, const float* __restrict__ fb2,
    const float* __restrict__ gw1, const float* __restrict__ gb1,
    const float* __restrict__ gw2, const float* __restrict__ gb2,
    float* __restrict__ out)
{
    extern __shared__ float sm1[];
    float* sFW1 = sm1;                  // 64*64
    float* sFW2 = sFW1 + 64*64;         // 64*128
    float* sGW1 = sFW2 + 64*128;        // 64*128  (collapsed)
    float* sGW2 = sGW1 + 64*128;        // 128*128
    float* sX   = sGW2 + 128*128;       // 64*65   (padded)
    float* sH   = sX   + 64*65;         // 64*129  (padded)

    const int t = threadIdx.x;
    for (int i = t; i < 64*64;   i += 256) sFW1[i] = fw1[i];
    for (int i = t; i < 64*128;  i += 256) sFW2[i] = fw2[i];
    for (int i = t; i < 64*128;  i += 256) {
        int k = i >> 7, j = i & 127;
        sGW1[i] = gw1[k*128 + j] + gw1[(k + 64)*128 + j];
    }
    for (int i = t; i < 128*128; i += 256) sGW2[i] = gw2[i];

    const int nodeBase = blockIdx.x * 64;
    for (int i = t; i < 64*64; i += 256) {
        int nd = i >> 6, k = i & 63;
        sX[nd*65 + k] = x[(size_t)(nodeBase + nd)*64 + k];
    }
    __syncthreads();

    const int lane8 = t & 7;
    const int grp   = t >> 3;          // 0..31
    const int nd0 = grp, nd1 = grp + 32;

    // ---- f layer 1: 64 -> 64, ReLU, -> sH[0..63] ----
    {
        const int jo = lane8 * 8;
        float a0[8], a1[8];
        #pragma unroll
        for (int u = 0; u < 8; u++) { float b = fb1[jo + u]; a0[u] = b; a1[u] = b; }
        #pragma unroll 4
        for (int k = 0; k < 64; k++) {
            float x0 = sX[nd0*65 + k], x1 = sX[nd1*65 + k];
            float w[8];
            *(float4*)&w[0] = *(const float4*)&sFW1[k*64 + jo];
            *(float4*)&w[4] = *(const float4*)&sFW1[k*64 + jo + 4];
            #pragma unroll
            for (int u = 0; u < 8; u++) { a0[u] += x0 * w[u]; a1[u] += x1 * w[u]; }
        }
        #pragma unroll
        for (int u = 0; u < 8; u++) {
            sH[nd0*129 + jo + u] = fmaxf(a0[u], 0.f);
            sH[nd1*129 + jo + u] = fmaxf(a1[u], 0.f);
        }
    }
    __syncwarp();

    // ---- f layer 2: 64 -> 128, + b, -> out (self_dyn) ----
    {
        const int jo = lane8 * 16;
        float a0[16], a1[16];
        #pragma unroll
        for (int u = 0; u < 16; u++) { float b = fb2[jo + u]; a0[u] = b; a1[u] = b; }
        #pragma unroll 2
        for (int k = 0; k < 64; k++) {
            float h0 = sH[nd0*129 + k], h1 = sH[nd1*129 + k];
            float w[16];
            *(float4*)&w[0]  = *(const float4*)&sFW2[k*128 + jo];
            *(float4*)&w[4]  = *(const float4*)&sFW2[k*128 + jo + 4];
            *(float4*)&w[8]  = *(const float4*)&sFW2[k*128 + jo + 8];
            *(float4*)&w[12] = *(const float4*)&sFW2[k*128 + jo + 12];
            #pragma unroll
            for (int u = 0; u < 16; u++) { a0[u] += h0 * w[u]; a1[u] += h1 * w[u]; }
        }
        #pragma unroll
        for (int q = 0; q < 4; q++) {
            *(float4*)&out[(size_t)(nodeBase + nd0)*128 + jo + q*4] =
                make_float4(a0[q*4], a0[q*4+1], a0[q*4+2], a0[q*4+3]);
            *(float4*)&out[(size_t)(nodeBase + nd1)*128 + jo + q*4] =
                make_float4(a1[q*4], a1[q*4+1], a1[q*4+2], a1[q*4+3]);
        }
    }
    __syncwarp();

    // ---- g layer 1: 64 -> 128 (collapsed), ReLU -> sH[0..127] ----
    {
        const int jo = lane8 * 16;
        float a0[16], a1[16];
        #pragma unroll
        for (int u = 0; u < 16; u++) { float b = gb1[jo + u]; a0[u] = b; a1[u] = b; }
        #pragma unroll 2
        for (int k = 0; k < 64; k++) {
            float x0 = sX[nd0*65 + k], x1 = sX[nd1*65 + k];
            float w[16];
            *(float4*)&w[0]  = *(const float4*)&sGW1[k*128 + jo];
            *(float4*)&w[4]  = *(const float4*)&sGW1[k*128 + jo + 4];
            *(float4*)&w[8]  = *(const float4*)&sGW1[k*128 + jo + 8];
            *(float4*)&w[12] = *(const float4*)&sGW1[k*128 + jo + 12];
            #pragma unroll
            for (int u = 0; u < 16; u++) { a0[u] += x0 * w[u]; a1[u] += x1 * w[u]; }
        }
        __syncwarp();   // everyone done reading old sH (f path)
        #pragma unroll
        for (int u = 0; u < 16; u++) {
            sH[nd0*129 + jo + u] = fmaxf(a0[u], 0.f);
            sH[nd1*129 + jo + u] = fmaxf(a1[u], 0.f);
        }
    }
    __syncwarp();

    // ---- g layer 2: 128 -> 128, + b, split to bf16 hi/lo -> g_ghi/g_glo ----
    {
        const int jo = lane8 * 16;
        float a0[16], a1[16];
        #pragma unroll
        for (int u = 0; u < 16; u++) { float b = gb2[jo + u]; a0[u] = b; a1[u] = b; }
        #pragma unroll 2
        for (int k = 0; k < 128; k++) {
            float h0 = sH[nd0*129 + k], h1 = sH[nd1*129 + k];
            float w[16];
            *(float4*)&w[0]  = *(const float4*)&sGW2[k*128 + jo];
            *(float4*)&w[4]  = *(const float4*)&sGW2[k*128 + jo + 4];
            *(float4*)&w[8]  = *(const float4*)&sGW2[k*128 + jo + 8];
            *(float4*)&w[12] = *(const float4*)&sGW2[k*128 + jo + 12];
            #pragma unroll
            for (int u = 0; u < 16; u++) { a0[u] += h0 * w[u]; a1[u] += h1 * w[u]; }
        }
        // split-store
        #pragma unroll
        for (int half = 0; half < 2; half++) {
            float* a = half ? a1 : a0;
            size_t base = (size_t)(nodeBase + (half ? nd1 : nd0))*128 + jo;
            uint32_t* ph = (uint32_t*)(g_ghi + base);
            uint32_t* pl = (uint32_t*)(g_glo + base);
            #pragma unroll
            for (int q = 0; q < 8; q++) {
                float v0 = a[2*q], v1 = a[2*q+1];
                __nv_bfloat16 h0 = __float2bfloat16(v0);
                __nv_bfloat16 h1 = __float2bfloat16(v1);
                __nv_bfloat16 l0 = __float2bfloat16(v0 - __bfloat162float(h0));
                __nv_bfloat16 l1 = __float2bfloat16(v1 - __bfloat162float(h1));
                ph[q] = (uint32_t)__bfloat16_as_ushort(h0) |
                        ((uint32_t)__bfloat16_as_ushort(h1) << 16);
                pl[q] = (uint32_t)__bfloat16_as_ushort(l0) |
                        ((uint32_t)__bfloat16_as_ushort(l1) << 16);
            }
        }
    }
}

// ---------------------------------------------------------------------------
// Stage 2: out[n,j,h] += sum_i edge[n,i,j] * gx[n,i,h]
// Split-bf16 MMA: C += Eh*Gh + Eh*Gl + El*Gh (fp32 accumulate).
// Block = 256 thr (8 warps), tile BM=128(j) x BN=128(h), BK=32(i), double buffer.
// ---------------------------------------------------------------------------
#define BK  32
#define LDT 136   // 128 + 8 bf16 pad -> 272B rows, conflict-free ldmatrix

#define LDSM_X4_T(r0,r1,r2,r3,addr) \
    asm volatile("ldmatrix.sync.aligned.m8n8.x4.trans.shared.b16 {%0,%1,%2,%3}, [%4];" \
        : "=r"(r0),"=r"(r1),"=r"(r2),"=r"(r3) : "r"(addr))
#define LDSM_X2_T(r0,r1,addr) \
    asm volatile("ldmatrix.sync.aligned.m8n8.x2.trans.shared.b16 {%0,%1}, [%2];" \
        : "=r"(r0),"=r"(r1) : "r"(addr))
#define MMA16816(c,a,b) \
    asm volatile("mma.sync.aligned.m16n8k16.row.col.f32.bf16.bf16.f32 " \
        "{%0,%1,%2,%3}, {%4,%5,%6,%7}, {%8,%9}, {%0,%1,%2,%3};" \
        : "+f"(c[0]),"+f"(c[1]),"+f"(c[2]),"+f"(c[3]) \
        : "r"(a[0]),"r"(a[1]),"r"(a[2]),"r"(a[3]),"r"(b[0]),"r"(b[1]))

__global__ __launch_bounds__(256) void stage2_kernel(
    const float* __restrict__ edge, float* __restrict__ out)
{
    extern __shared__ __nv_bfloat16 sm2[];
    __nv_bfloat16* sE = sm2;                    // [2 buf][2 hi/lo][BK][LDT]
    __nv_bfloat16* sG = sm2 + 2*2*BK*LDT;

    const int n  = blockIdx.y;
    const int j0 = blockIdx.x * 128;
    const int t = threadIdx.x, lane = t & 31, wid = t >> 5;
    const int wm = wid >> 2, wn = wid & 3;

    const float* eg = edge + (size_t)n*MM*MM + j0;
    const __nv_bfloat16* gh = g_ghi + (size_t)n*MM*DH;
    const __nv_bfloat16* gl = g_glo + (size_t)n*MM*DH;

    const int li = t >> 5;          // 0..7
    const int lj = (t & 31) * 4;    // 0..124

    float acc[4][4][4];
    #pragma unroll
    for (int a = 0; a < 4; a++)
        #pragma unroll
        for (int b = 0; b < 4; b++)
            #pragma unroll
            for (int c = 0; c < 4; c++) acc[a][b][c] = 0.f;

    float4 er[4];
    uint2  ghr[4], glr[4];

    uint32_t sEb = (uint32_t)__cvta_generic_to_shared(sE);
    uint32_t sGb = (uint32_t)__cvta_generic_to_shared(sG);
    const int aq1      = ((lane >> 3) & 1) << 3;
    const int arow_off = (((lane >> 4) & 1) << 3) + (lane & 7);
    const int brow_off = lane & 15;

    // prologue load of chunk 0
    #pragma unroll
    for (int u = 0; u < 4; u++) {
        int i = u*8 + li;
        er[u]  = *(const float4*)&eg[(size_t)i*MM + lj];
        ghr[u] = *(const uint2*)&gh[i*DH + lj];
        glr[u] = *(const uint2*)&gl[i*DH + lj];
    }

    for (int kt = 0; kt < MM/BK; kt++) {
        const int buf = kt & 1;
        // --- store regs -> smem (convert E to hi/lo) ---
        #pragma unroll
        for (int u = 0; u < 4; u++) {
            int si = u*8 + li;
            float4 v = er[u];
            __nv_bfloat16 h0 = __float2bfloat16(v.x);
            __nv_bfloat16 h1 = __float2bfloat16(v.y);
            __nv_bfloat16 h2 = __float2bfloat16(v.z);
            __nv_bfloat16 h3 = __float2bfloat16(v.w);
            __nv_bfloat16 l0 = __float2bfloat16(v.x - __bfloat162float(h0));
            __nv_bfloat16 l1 = __float2bfloat16(v.y - __bfloat162float(h1));
            __nv_bfloat16 l2 = __float2bfloat16(v.z - __bfloat162float(h2));
            __nv_bfloat16 l3 = __float2bfloat16(v.w - __bfloat162float(h3));
            uint2 hh, ll;
            hh.x = (uint32_t)__bfloat16_as_ushort(h0) | ((uint32_t)__bfloat16_as_ushort(h1) << 16);
            hh.y = (uint32_t)__bfloat16_as_ushort(h2) | ((uint32_t)__bfloat16_as_ushort(h3) << 16);
            ll.x = (uint32_t)__bfloat16_as_ushort(l0) | ((uint32_t)__bfloat16_as_ushort(l1) << 16);
            ll.y = (uint32_t)__bfloat16_as_ushort(l2) | ((uint32_t)__bfloat16_as_ushort(l3) << 16);
            *(uint2*)&sE[((buf*2 + 0)*BK + si)*LDT + lj] = hh;
            *(uint2*)&sE[((buf*2 + 1)*BK + si)*LDT + lj] = ll;
            *(uint2*)&sG[((buf*2 + 0)*BK + si)*LDT + lj] = ghr[u];
            *(uint2*)&sG[((buf*2 + 1)*BK + si)*LDT + lj] = glr[u];
        }
        __syncthreads();

        // --- prefetch next chunk into regs ---
        if (kt + 1 < MM/BK) {
            const int i0 = (kt + 1) * BK;
            #pragma unroll
            for (int u = 0; u < 4; u++) {
                int i = i0 + u*8 + li;
                er[u]  = *(const float4*)&eg[(size_t)i*MM + lj];
                ghr[u] = *(const uint2*)&gh[i*DH + lj];
                glr[u] = *(const uint2*)&gl[i*DH + lj];
            }
        }

        // --- compute on buf ---
        #pragma unroll
        for (int ks = 0; ks < BK; ks += 16) {
            uint32_t ah[4][4], al[4][4], bh[4][2], bl[4][2];
            #pragma unroll
            for (int mf = 0; mf < 4; mf++) {
                int acol = wm*64 + mf*16 + aq1;
                uint32_t ad0 = sEb + (uint32_t)((((buf*2 + 0)*BK + ks + arow_off)*LDT + acol) * 2);
                uint32_t ad1 = sEb + (uint32_t)((((buf*2 + 1)*BK + ks + arow_off)*LDT + acol) * 2);
                LDSM_X4_T(ah[mf][0], ah[mf][1], ah[mf][2], ah[mf][3], ad0);
                LDSM_X4_T(al[mf][0], al[mf][1], al[mf][2], al[mf][3], ad1);
            }
            #pragma unroll
            for (int nf = 0; nf < 4; nf++) {
                int bcol = wn*32 + nf*8;
                uint32_t bd0 = sGb + (uint32_t)((((buf*2 + 0)*BK + ks + brow_off)*LDT + bcol) * 2);
                uint32_t bd1 = sGb + (uint32_t)((((buf*2 + 1)*BK + ks + brow_off)*LDT + bcol) * 2);
                LDSM_X2_T(bh[nf][0], bh[nf][1], bd0);
                LDSM_X2_T(bl[nf][0], bl[nf][1], bd1);
            }
            #pragma unroll
            for (int mf = 0; mf < 4; mf++)
                #pragma unroll
                for (int nf = 0; nf < 4; nf++) MMA16816(acc[mf][nf], ah[mf], bh[nf]);
            #pragma unroll
            for (int mf = 0; mf < 4; mf++)
                #pragma unroll
                for (int nf = 0; nf < 4; nf++) MMA16816(acc[mf][nf], ah[mf], bl[nf]);
            #pragma unroll
            for (int mf = 0; mf < 4; mf++)
                #pragma unroll
                for (int nf = 0; nf < 4; nf++) MMA16816(acc[mf][nf], al[mf], bh[nf]);
        }
        __syncthreads();
    }

    // --- epilogue: out += acc (self_dyn already resident in out) ---
    const int r_base = j0 + wm*64;
    #pragma unroll
    for (int mf = 0; mf < 4; mf++) {
        int r0 = r_base + mf*16 + (lane >> 2);
        #pragma unroll
        for (int nf = 0; nf < 4; nf++) {
            int c = wn*32 + nf*8 + (lane & 3)*2;
            size_t o0 = ((size_t)n*MM + r0)*DH + c;
            float2 p0 = *(float2*)&out[o0];
            p0.x += acc[mf][nf][0]; p0.y += acc[mf][nf][1];
            *(float2*)&out[o0] = p0;
            size_t o1 = o0 + (size_t)8*DH;
            float2 p1 = *(float2*)&out[o1];
            p1.x += acc[mf][nf][2]; p1.y += acc[mf][nf][3];
            *(float2*)&out[o1] = p1;
        }
    }
}

// ---------------------------------------------------------------------------
extern "C" void kernel_launch(void* const* d_in, const int* in_sizes, int n_in,
                              void* d_out, int out_size)
{
    const float* x    = (const float*)d_in[0];
    const float* edge = (const float*)d_in[1];
    const float* fw1  = (const float*)d_in[2];
    const float* fb1  = (const float*)d_in[3];
    const float* fw2  = (const float*)d_in[4];
    const float* fb2  = (const float*)d_in[5];
    const float* gw1  = (const float*)d_in[6];
    const float* gb1  = (const float*)d_in[7];
    const float* gw2  = (const float*)d_in[8];
    const float* gb2  = (const float*)d_in[9];
    float* out = (float*)d_out;

    const int SMEM1 = (64*64 + 64*128 + 64*128 + 128*128 + 64*65 + 64*129) * 4; // 197120 B
    const int SMEM2 = (2*2*BK*LDT) * 2 /*bf16*/ * 2 /*E and G*/;                 // 69632 B

    cudaFuncSetAttribute(stage1_kernel, cudaFuncAttributeMaxDynamicSharedMemorySize, SMEM1);
    cudaFuncSetAttribute(stage2_kernel, cudaFuncAttributeMaxDynamicSharedMemorySize, SMEM2);

    stage1_kernel<<<NODES/64, 256, SMEM1>>>(x, fw1, fb1, fw2, fb2, gw1, gb1, gw2, gb2, out);
    stage2_kernel<<<dim3(MM/128, NB), 256, SMEM2>>>(edge, out);
}

// round 2
// speedup vs baseline: 1.9266x; 1.9266x over previous
#include <cuda_runtime.h>
#include <cuda_bf16.h>
#include <stdint.h>

#define NB   8
#define MM   2048
#define DIN  64
#define DH   128
#define NODES (NB*MM)

// scratch for gx as split bf16 (hi + lo)  — __device__ globals (no allocation)
__device__ __nv_bfloat16 g_ghi[NODES * DH];
__device__ __nv_bfloat16 g_glo[NODES * DH];

// ---------------------------------------------------------------------------
// Shared MMA macros
// ---------------------------------------------------------------------------
#define LDSM_X4(r0,r1,r2,r3,addr) \
    asm volatile("ldmatrix.sync.aligned.m8n8.x4.shared.b16 {%0,%1,%2,%3}, [%4];" \
        : "=r"(r0),"=r"(r1),"=r"(r2),"=r"(r3) : "r"(addr))
#define LDSM_X4_T(r0,r1,r2,r3,addr) \
    asm volatile("ldmatrix.sync.aligned.m8n8.x4.trans.shared.b16 {%0,%1,%2,%3}, [%4];" \
        : "=r"(r0),"=r"(r1),"=r"(r2),"=r"(r3) : "r"(addr))
#define LDSM_X2_T(r0,r1,addr) \
    asm volatile("ldmatrix.sync.aligned.m8n8.x2.trans.shared.b16 {%0,%1}, [%2];" \
        : "=r"(r0),"=r"(r1) : "r"(addr))
#define MMA16816(c,a,b) \
    asm volatile("mma.sync.aligned.m16n8k16.row.col.f32.bf16.bf16.f32 " \
        "{%0,%1,%2,%3}, {%4,%5,%6,%7}, {%8,%9}, {%0,%1,%2,%3};" \
        : "+f"(c[0]),"+f"(c[1]),"+f"(c[2]),"+f"(c[3]) \
        : "r"(a[0]),"r"(a[1]),"r"(a[2]),"r"(a[3]),"r"(b[0]),"r"(b[1]))

__device__ __forceinline__ void split2(float v0, float v1, uint32_t& hi, uint32_t& lo)
{
    __nv_bfloat16 h0 = __float2bfloat16(v0);
    __nv_bfloat16 h1 = __float2bfloat16(v1);
    __nv_bfloat16 l0 = __float2bfloat16(v0 - __bfloat162float(h0));
    __nv_bfloat16 l1 = __float2bfloat16(v1 - __bfloat162float(h1));
    hi = (uint32_t)__bfloat16_as_ushort(h0) | ((uint32_t)__bfloat16_as_ushort(h1) << 16);
    lo = (uint32_t)__bfloat16_as_ushort(l0) | ((uint32_t)__bfloat16_as_ushort(l1) << 16);
}

// ===========================================================================
// Stage 1 (MMA): all four MLP layers as split-bf16 tensor-core GEMMs.
// 128 blocks x 256 thr; each block owns 128 node-rows, chains layers in smem.
// ===========================================================================
#define S1_LDT 136
#define S1_PS  (128*S1_LDT)   // one bf16 plane

template<int NF, int KS>
__device__ __forceinline__ void mma_compute(float acc[][4],
    uint32_t aHi, uint32_t aLo, uint32_t wHi, uint32_t wLo,
    int arow, int acolofs, int brow)
{
    #pragma unroll
    for (int ks = 0; ks < KS; ks++) {
        uint32_t ah[4], al[4];
        uint32_t aoff = (uint32_t)((arow*S1_LDT + ks*16 + acolofs) * 2);
        LDSM_X4(ah[0], ah[1], ah[2], ah[3], aHi + aoff);
        LDSM_X4(al[0], al[1], al[2], al[3], aLo + aoff);
        #pragma unroll
        for (int nf = 0; nf < NF; nf++) {
            uint32_t bh[2], bl[2];
            uint32_t boff = (uint32_t)(((ks*16 + brow)*S1_LDT + nf*8) * 2);
            LDSM_X2_T(bh[0], bh[1], wHi + boff);
            LDSM_X2_T(bl[0], bl[1], wLo + boff);
            MMA16816(acc[nf], ah, bh);
            MMA16816(acc[nf], ah, bl);
            MMA16816(acc[nf], al, bh);
        }
    }
}

template<int NF>
__device__ __forceinline__ void init_bias(float acc[][4], const float* __restrict__ b, int lane)
{
    #pragma unroll
    for (int nf = 0; nf < NF; nf++) {
        int c = nf*8 + (lane & 3)*2;
        float b0 = b[c], b1 = b[c + 1];
        acc[nf][0] = b0; acc[nf][1] = b1; acc[nf][2] = b0; acc[nf][3] = b1;
    }
}

template<int NF>
__device__ __forceinline__ void epi_relu_split(float acc[][4],
    __nv_bfloat16* dHi, __nv_bfloat16* dLo, int m0, int lane)
{
    int r0 = m0 + (lane >> 2);
    #pragma unroll
    for (int nf = 0; nf < NF; nf++) {
        int c = nf*8 + (lane & 3)*2;
        uint32_t hi, lo;
        split2(fmaxf(acc[nf][0], 0.f), fmaxf(acc[nf][1], 0.f), hi, lo);
        *(uint32_t*)&dHi[r0*S1_LDT + c] = hi;
        *(uint32_t*)&dLo[r0*S1_LDT + c] = lo;
        split2(fmaxf(acc[nf][2], 0.f), fmaxf(acc[nf][3], 0.f), hi, lo);
        *(uint32_t*)&dHi[(r0 + 8)*S1_LDT + c] = hi;
        *(uint32_t*)&dLo[(r0 + 8)*S1_LDT + c] = lo;
    }
}

// load W[K][N] (optionally + w2, for collapsed g_w1) -> split planes
__device__ __forceinline__ void load_weight(const float* __restrict__ w,
    const float* __restrict__ w2, int K, int N,
    __nv_bfloat16* wHi, __nv_bfloat16* wLo, int t)
{
    int total = K * N / 2;
    for (int idx = t; idx < total; idx += 256) {
        int k  = idx / (N/2);
        int n2 = (idx - k*(N/2)) * 2;
        float v0 = w[k*N + n2], v1 = w[k*N + n2 + 1];
        if (w2) { v0 += w2[k*N + n2]; v1 += w2[k*N + n2 + 1]; }
        uint32_t hi, lo;
        split2(v0, v1, hi, lo);
        *(uint32_t*)&wHi[k*S1_LDT + n2] = hi;
        *(uint32_t*)&wLo[k*S1_LDT + n2] = lo;
    }
}

__global__ __launch_bounds__(256) void stage1_mma_kernel(
    const float* __restrict__ x,
    const float* __restrict__ fw1, const float* __restrict__ fb1,
    const float* __restrict__ fw2, const float* __restrict__ fb2,
    const float* __restrict__ gw1, const float* __restrict__ gb1,
    const float* __restrict__ gw2, const float* __restrict__ gb2,
    float* __restrict__ out)
{
    extern __shared__ __nv_bfloat16 s1[];
    __nv_bfloat16* wHi  = s1;
    __nv_bfloat16* wLo  = s1 + S1_PS;
    __nv_bfloat16* a0Hi = s1 + 2*S1_PS;   // x tile
    __nv_bfloat16* a0Lo = s1 + 3*S1_PS;
    __nv_bfloat16* a1Hi = s1 + 4*S1_PS;   // hidden tile
    __nv_bfloat16* a1Lo = s1 + 5*S1_PS;

    const int t = threadIdx.x, lane = t & 31, wid = t >> 5;
    const int m0 = wid * 16;
    const int arow = m0 + (lane & 15);
    const int acolofs = ((lane >> 4) & 1) * 8;
    const int brow = lane & 15;
    const int nodeBase = blockIdx.x * 128;

    const uint32_t wHiA  = (uint32_t)__cvta_generic_to_shared(wHi);
    const uint32_t wLoA  = (uint32_t)__cvta_generic_to_shared(wLo);
    const uint32_t a0HiA = (uint32_t)__cvta_generic_to_shared(a0Hi);
    const uint32_t a0LoA = (uint32_t)__cvta_generic_to_shared(a0Lo);
    const uint32_t a1HiA = (uint32_t)__cvta_generic_to_shared(a1Hi);
    const uint32_t a1LoA = (uint32_t)__cvta_generic_to_shared(a1Lo);

    // --- load x tile [128 x 64] (split) + w1f ---
    for (int idx = t; idx < 128*64/2; idx += 256) {
        int r  = idx >> 5;                // 32 pairs per row
        int c2 = (idx & 31) * 2;
        float2 v = *(const float2*)&x[(size_t)(nodeBase + r)*DIN + c2];
        uint32_t hi, lo;
        split2(v.x, v.y, hi, lo);
        *(uint32_t*)&a0Hi[r*S1_LDT + c2] = hi;
        *(uint32_t*)&a0Lo[r*S1_LDT + c2] = lo;
    }
    load_weight(fw1, nullptr, 64, 64, wHi, wLo, t);
    __syncthreads();

    // --- f layer 1: [128x64]*[64x64] + b, ReLU -> a1 ---
    {
        float acc[8][4];
        init_bias<8>(acc, fb1, lane);
        mma_compute<8,4>(acc, a0HiA, a0LoA, wHiA, wLoA, arow, acolofs, brow);
        epi_relu_split<8>(acc, a1Hi, a1Lo, m0, lane);
    }
    __syncthreads();
    load_weight(fw2, nullptr, 64, 128, wHi, wLo, t);
    __syncthreads();

    // --- f layer 2: [128x64]*[64x128] + b -> out (self_dyn) ---
    {
        float acc[16][4];
        init_bias<16>(acc, fb2, lane);
        mma_compute<16,4>(acc, a1HiA, a1LoA, wHiA, wLoA, arow, acolofs, brow);
        int r0 = nodeBase + m0 + (lane >> 2);
        #pragma unroll
        for (int nf = 0; nf < 16; nf++) {
            int c = nf*8 + (lane & 3)*2;
            *(float2*)&out[(size_t)r0*DH + c]       = make_float2(acc[nf][0], acc[nf][1]);
            *(float2*)&out[(size_t)(r0 + 8)*DH + c] = make_float2(acc[nf][2], acc[nf][3]);
        }
    }
    __syncthreads();
    load_weight(gw1, gw1 + 64*DH, 64, 128, wHi, wLo, t);  // collapsed
    __syncthreads();

    // --- g layer 1: [128x64]*[64x128] + b, ReLU -> a1 ---
    {
        float acc[16][4];
        init_bias<16>(acc, gb1, lane);
        mma_compute<16,4>(acc, a0HiA, a0LoA, wHiA, wLoA, arow, acolofs, brow);
        epi_relu_split<16>(acc, a1Hi, a1Lo, m0, lane);
    }
    __syncthreads();
    load_weight(gw2, nullptr, 128, 128, wHi, wLo, t);
    __syncthreads();

    // --- g layer 2: [128x128]*[128x128] + b -> gx split (global) ---
    {
        float acc[16][4];
        init_bias<16>(acc, gb2, lane);
        mma_compute<16,8>(acc, a1HiA, a1LoA, wHiA, wLoA, arow, acolofs, brow);
        int r0 = nodeBase + m0 + (lane >> 2);
        #pragma unroll
        for (int nf = 0; nf < 16; nf++) {
            int c = nf*8 + (lane & 3)*2;
            uint32_t hi, lo;
            split2(acc[nf][0], acc[nf][1], hi, lo);
            *(uint32_t*)&g_ghi[(size_t)r0*DH + c] = hi;
            *(uint32_t*)&g_glo[(size_t)r0*DH + c] = lo;
            split2(acc[nf][2], acc[nf][3], hi, lo);
            *(uint32_t*)&g_ghi[(size_t)(r0 + 8)*DH + c] = hi;
            *(uint32_t*)&g_glo[(size_t)(r0 + 8)*DH + c] = lo;
        }
    }
}

// ---------------------------------------------------------------------------
// Stage 2: out[n,j,h] += sum_i edge[n,i,j] * gx[n,i,h]
// Split-bf16 MMA: C += Eh*Gh + Eh*Gl + El*Gh (fp32 accumulate).
// Block = 256 thr (8 warps), tile BM=128(j) x BN=128(h), BK=32(i), double buffer.
// ---------------------------------------------------------------------------
#define BK  32
#define LDT 136   // 128 + 8 bf16 pad -> 272B rows, conflict-free ldmatrix

__global__ __launch_bounds__(256) void stage2_kernel(
    const float* __restrict__ edge, float* __restrict__ out)
{
    extern __shared__ __nv_bfloat16 sm2[];
    __nv_bfloat16* sE = sm2;                    // [2 buf][2 hi/lo][BK][LDT]
    __nv_bfloat16* sG = sm2 + 2*2*BK*LDT;

    const int n  = blockIdx.y;
    const int j0 = blockIdx.x * 128;
    const int t = threadIdx.x, lane = t & 31, wid = t >> 5;
    const int wm = wid >> 2, wn = wid & 3;

    const float* eg = edge + (size_t)n*MM*MM + j0;
    const __nv_bfloat16* gh = g_ghi + (size_t)n*MM*DH;
    const __nv_bfloat16* gl = g_glo + (size_t)n*MM*DH;

    const int li = t >> 5;          // 0..7
    const int lj = (t & 31) * 4;    // 0..124

    float acc[4][4][4];
    #pragma unroll
    for (int a = 0; a < 4; a++)
        #pragma unroll
        for (int b = 0; b < 4; b++)
            #pragma unroll
            for (int c = 0; c < 4; c++) acc[a][b][c] = 0.f;

    float4 er[4];
    uint2  ghr[4], glr[4];

    uint32_t sEb = (uint32_t)__cvta_generic_to_shared(sE);
    uint32_t sGb = (uint32_t)__cvta_generic_to_shared(sG);
    const int aq1      = ((lane >> 3) & 1) << 3;
    const int arow_off = (((lane >> 4) & 1) << 3) + (lane & 7);
    const int brow_off = lane & 15;

    // prologue load of chunk 0
    #pragma unroll
    for (int u = 0; u < 4; u++) {
        int i = u*8 + li;
        er[u]  = *(const float4*)&eg[(size_t)i*MM + lj];
        ghr[u] = *(const uint2*)&gh[i*DH + lj];
        glr[u] = *(const uint2*)&gl[i*DH + lj];
    }

    for (int kt = 0; kt < MM/BK; kt++) {
        const int buf = kt & 1;
        // --- store regs -> smem (convert E to hi/lo) ---
        #pragma unroll
        for (int u = 0; u < 4; u++) {
            int si = u*8 + li;
            float4 v = er[u];
            __nv_bfloat16 h0 = __float2bfloat16(v.x);
            __nv_bfloat16 h1 = __float2bfloat16(v.y);
            __nv_bfloat16 h2 = __float2bfloat16(v.z);
            __nv_bfloat16 h3 = __float2bfloat16(v.w);
            __nv_bfloat16 l0 = __float2bfloat16(v.x - __bfloat162float(h0));
            __nv_bfloat16 l1 = __float2bfloat16(v.y - __bfloat162float(h1));
            __nv_bfloat16 l2 = __float2bfloat16(v.z - __bfloat162float(h2));
            __nv_bfloat16 l3 = __float2bfloat16(v.w - __bfloat162float(h3));
            uint2 hh, ll;
            hh.x = (uint32_t)__bfloat16_as_ushort(h0) | ((uint32_t)__bfloat16_as_ushort(h1) << 16);
            hh.y = (uint32_t)__bfloat16_as_ushort(h2) | ((uint32_t)__bfloat16_as_ushort(h3) << 16);
            ll.x = (uint32_t)__bfloat16_as_ushort(l0) | ((uint32_t)__bfloat16_as_ushort(l1) << 16);
            ll.y = (uint32_t)__bfloat16_as_ushort(l2) | ((uint32_t)__bfloat16_as_ushort(l3) << 16);
            *(uint2*)&sE[((buf*2 + 0)*BK + si)*LDT + lj] = hh;
            *(uint2*)&sE[((buf*2 + 1)*BK + si)*LDT + lj] = ll;
            *(uint2*)&sG[((buf*2 + 0)*BK + si)*LDT + lj] = ghr[u];
            *(uint2*)&sG[((buf*2 + 1)*BK + si)*LDT + lj] = glr[u];
        }
        __syncthreads();

        // --- prefetch next chunk into regs ---
        if (kt + 1 < MM/BK) {
            const int i0 = (kt + 1) * BK;
            #pragma unroll
            for (int u = 0; u < 4; u++) {
                int i = i0 + u*8 + li;
                er[u]  = *(const float4*)&eg[(size_t)i*MM + lj];
                ghr[u] = *(const uint2*)&gh[i*DH + lj];
                glr[u] = *(const uint2*)&gl[i*DH + lj];
            }
        }

        // --- compute on buf ---
        #pragma unroll
        for (int ks = 0; ks < BK; ks += 16) {
            uint32_t ah[4][4], al[4][4], bh[4][2], bl[4][2];
            #pragma unroll
            for (int mf = 0; mf < 4; mf++) {
                int acol = wm*64 + mf*16 + aq1;
                uint32_t ad0 = sEb + (uint32_t)((((buf*2 + 0)*BK + ks + arow_off)*LDT + acol) * 2);
                uint32_t ad1 = sEb + (uint32_t)((((buf*2 + 1)*BK + ks + arow_off)*LDT + acol) * 2);
                LDSM_X4_T(ah[mf][0], ah[mf][1], ah[mf][2], ah[mf][3], ad0);
                LDSM_X4_T(al[mf][0], al[mf][1], al[mf][2], al[mf][3], ad1);
            }
            #pragma unroll
            for (int nf = 0; nf < 4; nf++) {
                int bcol = wn*32 + nf*8;
                uint32_t bd0 = sGb + (uint32_t)((((buf*2 + 0)*BK + ks + brow_off)*LDT + bcol) * 2);
                uint32_t bd1 = sGb + (uint32_t)((((buf*2 + 1)*BK + ks + brow_off)*LDT + bcol) * 2);
                LDSM_X2_T(bh[nf][0], bh[nf][1], bd0);
                LDSM_X2_T(bl[nf][0], bl[nf][1], bd1);
            }
            #pragma unroll
            for (int mf = 0; mf < 4; mf++)
                #pragma unroll
                for (int nf = 0; nf < 4; nf++) MMA16816(acc[mf][nf], ah[mf], bh[nf]);
            #pragma unroll
            for (int mf = 0; mf < 4; mf++)
                #pragma unroll
                for (int nf = 0; nf < 4; nf++) MMA16816(acc[mf][nf], ah[mf], bl[nf]);
            #pragma unroll
            for (int mf = 0; mf < 4; mf++)
                #pragma unroll
                for (int nf = 0; nf < 4; nf++) MMA16816(acc[mf][nf], al[mf], bh[nf]);
        }
        __syncthreads();
    }

    // --- epilogue: out += acc (self_dyn already resident in out) ---
    const int r_base = j0 + wm*64;
    #pragma unroll
    for (int mf = 0; mf < 4; mf++) {
        int r0 = r_base + mf*16 + (lane >> 2);
        #pragma unroll
        for (int nf = 0; nf < 4; nf++) {
            int c = wn*32 + nf*8 + (lane & 3)*2;
            size_t o0 = ((size_t)n*MM + r0)*DH + c;
            float2 p0 = *(float2*)&out[o0];
            p0.x += acc[mf][nf][0]; p0.y += acc[mf][nf][1];
            *(float2*)&out[o0] = p0;
            size_t o1 = o0 + (size_t)8*DH;
            float2 p1 = *(float2*)&out[o1];
            p1.x += acc[mf][nf][2]; p1.y += acc[mf][nf][3];
            *(float2*)&out[o1] = p1;
        }
    }
}

// ---------------------------------------------------------------------------
extern "C" void kernel_launch(void* const* d_in, const int* in_sizes, int n_in,
                              void* d_out, int out_size)
{
    const float* x    = (const float*)d_in[0];
    const float* edge = (const float*)d_in[1];
    const float* fw1  = (const float*)d_in[2];
    const float* fb1  = (const float*)d_in[3];
    const float* fw2  = (const float*)d_in[4];
    const float* fb2  = (const float*)d_in[5];
    const float* gw1  = (const float*)d_in[6];
    const float* gb1  = (const float*)d_in[7];
    const float* gw2  = (const float*)d_in[8];
    const float* gb2  = (const float*)d_in[9];
    float* out = (float*)d_out;

    const int SMEM1 = 6 * S1_PS * 2;                          // 208896 B
    const int SMEM2 = (2*2*BK*LDT) * 2 /*bf16*/ * 2 /*E,G*/;  // 69632 B

    cudaFuncSetAttribute(stage1_mma_kernel, cudaFuncAttributeMaxDynamicSharedMemorySize, SMEM1);
    cudaFuncSetAttribute(stage2_kernel, cudaFuncAttributeMaxDynamicSharedMemorySize, SMEM2);

    stage1_mma_kernel<<<NODES/128, 256, SMEM1>>>(x, fw1, fb1, fw2, fb2, gw1, gb1, gw2, gb2, out);
    stage2_kernel<<<dim3(MM/128, NB), 256, SMEM2>>>(edge, out);
}

// round 3
// speedup vs baseline: 2.1069x; 1.0936x over previous
#include <cuda_runtime.h>
#include <cuda_bf16.h>
#include <stdint.h>

#define NB   8
#define MM   2048
#define DIN  64
#define DH   128
#define NODES (NB*MM)

// scratch for gx as split bf16 (hi + lo)
__device__ __align__(16) __nv_bfloat16 g_ghi[NODES * DH];
__device__ __align__(16) __nv_bfloat16 g_glo[NODES * DH];

// ---------------------------------------------------------------------------
#define LDSM_X4(r0,r1,r2,r3,addr) \
    asm volatile("ldmatrix.sync.aligned.m8n8.x4.shared.b16 {%0,%1,%2,%3}, [%4];" \
        : "=r"(r0),"=r"(r1),"=r"(r2),"=r"(r3) : "r"(addr))
#define LDSM_X4_T(r0,r1,r2,r3,addr) \
    asm volatile("ldmatrix.sync.aligned.m8n8.x4.trans.shared.b16 {%0,%1,%2,%3}, [%4];" \
        : "=r"(r0),"=r"(r1),"=r"(r2),"=r"(r3) : "r"(addr))
#define MMA16816(c,a,b) \
    asm volatile("mma.sync.aligned.m16n8k16.row.col.f32.bf16.bf16.f32 " \
        "{%0,%1,%2,%3}, {%4,%5,%6,%7}, {%8,%9}, {%0,%1,%2,%3};" \
        : "+f"(c[0]),"+f"(c[1]),"+f"(c[2]),"+f"(c[3]) \
        : "r"(a[0]),"r"(a[1]),"r"(a[2]),"r"(a[3]),"r"(b[0]),"r"(b[1]))
#define CP_ASYNC16(dst,src) \
    asm volatile("cp.async.cg.shared.global [%0], [%1], 16;" :: "r"(dst), "l"(src))
#define CP_COMMIT() asm volatile("cp.async.commit_group;")
#define CP_WAIT0()  asm volatile("cp.async.wait_group 0;")

__device__ __forceinline__ void split2(float v0, float v1, uint32_t& hi, uint32_t& lo)
{
    __nv_bfloat16 h0 = __float2bfloat16(v0);
    __nv_bfloat16 h1 = __float2bfloat16(v1);
    __nv_bfloat16 l0 = __float2bfloat16(v0 - __bfloat162float(h0));
    __nv_bfloat16 l1 = __float2bfloat16(v1 - __bfloat162float(h1));
    hi = (uint32_t)__bfloat16_as_ushort(h0) | ((uint32_t)__bfloat16_as_ushort(h1) << 16);
    lo = (uint32_t)__bfloat16_as_ushort(l0) | ((uint32_t)__bfloat16_as_ushort(l1) << 16);
}

// ===========================================================================
// Stage 1: f-path blocks (0..255) and g-path blocks (256..511), 64 rows each.
// ===========================================================================
#define W_LDT  136
#define A0_LDT 72
#define A1_LDT 136
#define W_PS   (64*W_LDT)
#define A0_PS  (64*A0_LDT)
#define A1_PS  (64*A1_LDT)

// A: m16k16 row-major frags from smem plane; B: weight planes [k][n] (trans x4)
template<int NFR>   // NFR = per-warp n8 fragments (per-warp span = NFR*8 cols)
__device__ __forceinline__ void mma_pass(
    float acc[2][NFR][4],
    uint32_t aHiA, uint32_t aLoA, int aLDT, int kColOfs,
    uint32_t wHiA, uint32_t wLoA,
    int lane, int wm, int wn)
{
    const int arow = wm*32 + (lane & 15);
    const int aq   = ((lane >> 4) & 1) * 8;
    const int bq   = ((lane >> 4) & 1) * 8;
    #pragma unroll
    for (int ks = 0; ks < 4; ks++) {
        uint32_t ah[2][4], al[2][4];
        #pragma unroll
        for (int mf = 0; mf < 2; mf++) {
            uint32_t ao = (uint32_t)(((arow + mf*16)*aLDT + kColOfs + ks*16 + aq) * 2);
            LDSM_X4(ah[mf][0], ah[mf][1], ah[mf][2], ah[mf][3], aHiA + ao);
            LDSM_X4(al[mf][0], al[mf][1], al[mf][2], al[mf][3], aLoA + ao);
        }
        uint32_t bh[(NFR+1)/2][4], bl[(NFR+1)/2][4];
        #pragma unroll
        for (int nf2 = 0; nf2 < (NFR+1)/2; nf2++) {
            uint32_t bo = (uint32_t)((((ks*16) + (lane & 15))*W_LDT + wn*NFR*8 + nf2*16 + bq) * 2);
            LDSM_X4_T(bh[nf2][0], bh[nf2][1], bh[nf2][2], bh[nf2][3], wHiA + bo);
            LDSM_X4_T(bl[nf2][0], bl[nf2][1], bl[nf2][2], bl[nf2][3], wLoA + bo);
        }
        #pragma unroll
        for (int mf = 0; mf < 2; mf++)
            #pragma unroll
            for (int nf = 0; nf < NFR; nf++) {
                uint32_t* bhf = &bh[nf>>1][(nf&1)*2];
                uint32_t* blf = &bl[nf>>1][(nf&1)*2];
                MMA16816(acc[mf][nf], ah[mf], bhf);
                MMA16816(acc[mf][nf], ah[mf], blf);
                MMA16816(acc[mf][nf], al[mf], bhf);
            }
    }
}

template<int NFR>
__device__ __forceinline__ void init_bias(float acc[2][NFR][4],
    const float* __restrict__ b, int lane, int wn)
{
    #pragma unroll
    for (int nf = 0; nf < NFR; nf++) {
        int c = wn*NFR*8 + nf*8 + (lane & 3)*2;
        float b0 = b[c], b1 = b[c + 1];
        #pragma unroll
        for (int mf = 0; mf < 2; mf++) {
            acc[mf][nf][0] = b0; acc[mf][nf][1] = b1;
            acc[mf][nf][2] = b0; acc[mf][nf][3] = b1;
        }
    }
}

template<int NFR>
__device__ __forceinline__ void epi_relu_split(float acc[2][NFR][4],
    __nv_bfloat16* dHi, __nv_bfloat16* dLo, int ldt, int lane, int wm, int wn)
{
    #pragma unroll
    for (int mf = 0; mf < 2; mf++) {
        int r0 = wm*32 + mf*16 + (lane >> 2);
        #pragma unroll
        for (int nf = 0; nf < NFR; nf++) {
            int c = wn*NFR*8 + nf*8 + (lane & 3)*2;
            uint32_t hi, lo;
            split2(fmaxf(acc[mf][nf][0], 0.f), fmaxf(acc[mf][nf][1], 0.f), hi, lo);
            *(uint32_t*)&dHi[r0*ldt + c] = hi;
            *(uint32_t*)&dLo[r0*ldt + c] = lo;
            split2(fmaxf(acc[mf][nf][2], 0.f), fmaxf(acc[mf][nf][3], 0.f), hi, lo);
            *(uint32_t*)&dHi[(r0 + 8)*ldt + c] = hi;
            *(uint32_t*)&dLo[(r0 + 8)*ldt + c] = lo;
        }
    }
}

__device__ __forceinline__ void load_weight64(const float* __restrict__ w,
    const float* __restrict__ w2, int K, int N,
    __nv_bfloat16* wHi, __nv_bfloat16* wLo, int t)
{
    int total = K * N / 2;
    for (int idx = t; idx < total; idx += 256) {
        int k  = idx / (N/2);
        int n2 = (idx - k*(N/2)) * 2;
        float v0 = w[k*N + n2], v1 = w[k*N + n2 + 1];
        if (w2) { v0 += w2[k*N + n2]; v1 += w2[k*N + n2 + 1]; }
        uint32_t hi, lo;
        split2(v0, v1, hi, lo);
        *(uint32_t*)&wHi[k*W_LDT + n2] = hi;
        *(uint32_t*)&wLo[k*W_LDT + n2] = lo;
    }
}

__global__ __launch_bounds__(256) void stage1_kernel(
    const float* __restrict__ x,
    const float* __restrict__ fw1, const float* __restrict__ fb1,
    const float* __restrict__ fw2, const float* __restrict__ fb2,
    const float* __restrict__ gw1, const float* __restrict__ gb1,
    const float* __restrict__ gw2, const float* __restrict__ gb2,
    float* __restrict__ out)
{
    extern __shared__ __nv_bfloat16 s1[];
    __nv_bfloat16* wHi  = s1;
    __nv_bfloat16* wLo  = wHi  + W_PS;
    __nv_bfloat16* a0Hi = wLo  + W_PS;
    __nv_bfloat16* a0Lo = a0Hi + A0_PS;
    __nv_bfloat16* a1Hi = a0Lo + A0_PS;
    __nv_bfloat16* a1Lo = a1Hi + A1_PS;

    const int t = threadIdx.x, lane = t & 31, wid = t >> 5;
    const int wm = wid >> 2, wn = wid & 3;
    const bool fpath = (blockIdx.x < 256);
    const int nodeBase = (blockIdx.x & 255) * 64;

    const uint32_t wHiA  = (uint32_t)__cvta_generic_to_shared(wHi);
    const uint32_t wLoA  = (uint32_t)__cvta_generic_to_shared(wLo);
    const uint32_t a0HiA = (uint32_t)__cvta_generic_to_shared(a0Hi);
    const uint32_t a0LoA = (uint32_t)__cvta_generic_to_shared(a0Lo);
    const uint32_t a1HiA = (uint32_t)__cvta_generic_to_shared(a1Hi);
    const uint32_t a1LoA = (uint32_t)__cvta_generic_to_shared(a1Lo);

    // load x tile [64 x 64] split
    for (int idx = t; idx < 64*64/2; idx += 256) {
        int r  = idx >> 5;
        int c2 = (idx & 31) * 2;
        float2 v = *(const float2*)&x[(size_t)(nodeBase + r)*DIN + c2];
        uint32_t hi, lo;
        split2(v.x, v.y, hi, lo);
        *(uint32_t*)&a0Hi[r*A0_LDT + c2] = hi;
        *(uint32_t*)&a0Lo[r*A0_LDT + c2] = lo;
    }

    if (fpath) {
        load_weight64(fw1, nullptr, 64, 64, wHi, wLo, t);
        __syncthreads();
        {   // f1: [64x64]*[64x64] relu -> a1
            float acc[2][2][4];
            init_bias<2>(acc, fb1, lane, wn);
            mma_pass<2>(acc, a0HiA, a0LoA, A0_LDT, 0, wHiA, wLoA, lane, wm, wn);
            epi_relu_split<2>(acc, a1Hi, a1Lo, A1_LDT, lane, wm, wn);
        }
        __syncthreads();
        load_weight64(fw2, nullptr, 64, 128, wHi, wLo, t);
        __syncthreads();
        {   // f2: [64x64]*[64x128] -> out
            float acc[2][4][4];
            init_bias<4>(acc, fb2, lane, wn);
            mma_pass<4>(acc, a1HiA, a1LoA, A1_LDT, 0, wHiA, wLoA, lane, wm, wn);
            #pragma unroll
            for (int mf = 0; mf < 2; mf++) {
                int r0 = nodeBase + wm*32 + mf*16 + (lane >> 2);
                #pragma unroll
                for (int nf = 0; nf < 4; nf++) {
                    int c = wn*32 + nf*8 + (lane & 3)*2;
                    *(float2*)&out[(size_t)r0*DH + c]       = make_float2(acc[mf][nf][0], acc[mf][nf][1]);
                    *(float2*)&out[(size_t)(r0 + 8)*DH + c] = make_float2(acc[mf][nf][2], acc[mf][nf][3]);
                }
            }
        }
    } else {
        load_weight64(gw1, gw1 + 64*DH, 64, 128, wHi, wLo, t);  // collapsed g_w1
        __syncthreads();
        {   // g1: [64x64]*[64x128] relu -> a1
            float acc[2][4][4];
            init_bias<4>(acc, gb1, lane, wn);
            mma_pass<4>(acc, a0HiA, a0LoA, A0_LDT, 0, wHiA, wLoA, lane, wm, wn);
            epi_relu_split<4>(acc, a1Hi, a1Lo, A1_LDT, lane, wm, wn);
        }
        __syncthreads();
        load_weight64(gw2, nullptr, 64, 128, wHi, wLo, t);       // rows 0..63
        __syncthreads();
        float acc[2][4][4];
        init_bias<4>(acc, gb2, lane, wn);
        mma_pass<4>(acc, a1HiA, a1LoA, A1_LDT, 0, wHiA, wLoA, lane, wm, wn);
        __syncthreads();
        load_weight64(gw2 + 64*DH, nullptr, 64, 128, wHi, wLo, t); // rows 64..127
        __syncthreads();
        mma_pass<4>(acc, a1HiA, a1LoA, A1_LDT, 64, wHiA, wLoA, lane, wm, wn);
        // epilogue: split to global gx planes
        #pragma unroll
        for (int mf = 0; mf < 2; mf++) {
            int r0 = nodeBase + wm*32 + mf*16 + (lane >> 2);
            #pragma unroll
            for (int nf = 0; nf < 4; nf++) {
                int c = wn*32 + nf*8 + (lane & 3)*2;
                uint32_t hi, lo;
                split2(acc[mf][nf][0], acc[mf][nf][1], hi, lo);
                *(uint32_t*)&g_ghi[(size_t)r0*DH + c] = hi;
                *(uint32_t*)&g_glo[(size_t)r0*DH + c] = lo;
                split2(acc[mf][nf][2], acc[mf][nf][3], hi, lo);
                *(uint32_t*)&g_ghi[(size_t)(r0 + 8)*DH + c] = hi;
                *(uint32_t*)&g_glo[(size_t)(r0 + 8)*DH + c] = lo;
            }
        }
    }
}

// ===========================================================================
// Stage 2: out[n,j,h] += sum_i edge[n,i,j]*gx[n,i,h]; 3-term split-bf16 MMA.
// grid (32, 8): BM=64 (j) x BN=128 (h), BK=32, double buffer, 1 sync/iter.
// ===========================================================================
#define BK    32
#define EPAD  72
#define GPAD  136
#define SE_PS (BK*EPAD)     // one E plane
#define SG_PS (BK*GPAD)     // one G plane

__global__ __launch_bounds__(256) void stage2_kernel(
    const float* __restrict__ edge, float* __restrict__ out)
{
    extern __shared__ __nv_bfloat16 sm2[];
    __nv_bfloat16* sE = sm2;                  // [2 buf][2 pl][BK][EPAD]
    __nv_bfloat16* sG = sm2 + 2*2*SE_PS;      // [2 buf][2 pl][BK][GPAD]

    const int n  = blockIdx.y;
    const int j0 = blockIdx.x * 64;
    const int t = threadIdx.x, lane = t & 31, wid = t >> 5;
    const int wm = wid >> 2, wn = wid & 3;

    const float* eg = edge + (size_t)n*MM*MM + j0;
    const __nv_bfloat16* gh = g_ghi + (size_t)n*MM*DH;
    const __nv_bfloat16* gl = g_glo + (size_t)n*MM*DH;

    const uint32_t sEb = (uint32_t)__cvta_generic_to_shared(sE);
    const uint32_t sGb = (uint32_t)__cvta_generic_to_shared(sG);

    const int ldrow = t >> 4;          // 0..15 (and +16)
    const int ecol  = (t & 15) * 4;    // E float4 col
    const int gcol  = (t & 15) * 8;    // G 16B col

    const int arow_off = ((lane >> 4) & 1)*8 + (lane & 7);
    const int aq1      = ((lane >> 3) & 1)*8;
    const int bq       = ((lane >> 4) & 1)*8;

    float acc[2][4][4];
    #pragma unroll
    for (int a = 0; a < 2; a++)
        #pragma unroll
        for (int b = 0; b < 4; b++)
            #pragma unroll
            for (int c = 0; c < 4; c++) acc[a][b][c] = 0.f;

    float4 er[2];

    // ---- prologue: chunk 0 into buf 0 ----
    #pragma unroll
    for (int u = 0; u < 2; u++) {
        int row = ldrow + u*16;
        CP_ASYNC16(sGb + (uint32_t)(((0*2 + 0)*BK + row)*GPAD + gcol)*2, gh + (size_t)row*DH + gcol);
        CP_ASYNC16(sGb + (uint32_t)(((0*2 + 1)*BK + row)*GPAD + gcol)*2, gl + (size_t)row*DH + gcol);
    }
    CP_COMMIT();
    #pragma unroll
    for (int u = 0; u < 2; u++)
        er[u] = *(const float4*)&eg[(size_t)(ldrow + u*16)*MM + ecol];
    #pragma unroll
    for (int u = 0; u < 2; u++) {
        int row = ldrow + u*16;
        float4 v = er[u];
        uint32_t h0, l0, h1, l1;
        split2(v.x, v.y, h0, l0);
        split2(v.z, v.w, h1, l1);
        *(uint2*)&sE[((0*2 + 0)*BK + row)*EPAD + ecol] = make_uint2(h0, h1);
        *(uint2*)&sE[((0*2 + 1)*BK + row)*EPAD + ecol] = make_uint2(l0, l1);
    }
    CP_WAIT0();

    for (int kt = 0; kt < MM/BK; kt++) {
        const int buf = kt & 1;
        __syncthreads();

        // prefetch chunk kt+1 into buf^1
        if (kt + 1 < MM/BK) {
            const int i0 = (kt + 1) * BK;
            #pragma unroll
            for (int u = 0; u < 2; u++) {
                int row = ldrow + u*16;
                CP_ASYNC16(sGb + (uint32_t)((((buf^1)*2 + 0)*BK + row)*GPAD + gcol)*2,
                           gh + (size_t)(i0 + row)*DH + gcol);
                CP_ASYNC16(sGb + (uint32_t)((((buf^1)*2 + 1)*BK + row)*GPAD + gcol)*2,
                           gl + (size_t)(i0 + row)*DH + gcol);
            }
            CP_COMMIT();
            #pragma unroll
            for (int u = 0; u < 2; u++)
                er[u] = *(const float4*)&eg[(size_t)(i0 + ldrow + u*16)*MM + ecol];
        }

        // compute on buf
        #pragma unroll
        for (int ks = 0; ks < BK; ks += 16) {
            uint32_t ah[2][4], al[2][4];
            #pragma unroll
            for (int mf = 0; mf < 2; mf++) {
                int acol = wm*32 + mf*16 + aq1;
                uint32_t a0 = sEb + (uint32_t)((((buf*2 + 0)*BK + ks + arow_off)*EPAD + acol)*2);
                uint32_t a1 = sEb + (uint32_t)((((buf*2 + 1)*BK + ks + arow_off)*EPAD + acol)*2);
                LDSM_X4_T(ah[mf][0], ah[mf][1], ah[mf][2], ah[mf][3], a0);
                LDSM_X4_T(al[mf][0], al[mf][1], al[mf][2], al[mf][3], a1);
            }
            uint32_t bh[2][4], bl[2][4];
            #pragma unroll
            for (int nf2 = 0; nf2 < 2; nf2++) {
                int bcol = wn*32 + nf2*16 + bq;
                uint32_t b0 = sGb + (uint32_t)((((buf*2 + 0)*BK + ks + (lane & 15))*GPAD + bcol)*2);
                uint32_t b1 = sGb + (uint32_t)((((buf*2 + 1)*BK + ks + (lane & 15))*GPAD + bcol)*2);
                LDSM_X4_T(bh[nf2][0], bh[nf2][1], bh[nf2][2], bh[nf2][3], b0);
                LDSM_X4_T(bl[nf2][0], bl[nf2][1], bl[nf2][2], bl[nf2][3], b1);
            }
            #pragma unroll
            for (int mf = 0; mf < 2; mf++)
                #pragma unroll
                for (int nf = 0; nf < 4; nf++) {
                    uint32_t* bhf = &bh[nf>>1][(nf&1)*2];
                    uint32_t* blf = &bl[nf>>1][(nf&1)*2];
                    MMA16816(acc[mf][nf], ah[mf], bhf);
                    MMA16816(acc[mf][nf], ah[mf], blf);
                    MMA16816(acc[mf][nf], al[mf], bhf);
                }
        }

        // store E chunk kt+1 into buf^1
        if (kt + 1 < MM/BK) {
            #pragma unroll
            for (int u = 0; u < 2; u++) {
                int row = ldrow + u*16;
                float4 v = er[u];
                uint32_t h0, l0, h1, l1;
                split2(v.x, v.y, h0, l0);
                split2(v.z, v.w, h1, l1);
                *(uint2*)&sE[(((buf^1)*2 + 0)*BK + row)*EPAD + ecol] = make_uint2(h0, h1);
                *(uint2*)&sE[(((buf^1)*2 + 1)*BK + row)*EPAD + ecol] = make_uint2(l0, l1);
            }
        }
        CP_WAIT0();
    }

    // epilogue: out += acc
    #pragma unroll
    for (int mf = 0; mf < 2; mf++) {
        int r0 = j0 + wm*32 + mf*16 + (lane >> 2);
        #pragma unroll
        for (int nf = 0; nf < 4; nf++) {
            int c = wn*32 + nf*8 + (lane & 3)*2;
            size_t o0 = ((size_t)n*MM + r0)*DH + c;
            float2 p0 = *(float2*)&out[o0];
            p0.x += acc[mf][nf][0]; p0.y += acc[mf][nf][1];
            *(float2*)&out[o0] = p0;
            size_t o1 = o0 + (size_t)8*DH;
            float2 p1 = *(float2*)&out[o1];
            p1.x += acc[mf][nf][2]; p1.y += acc[mf][nf][3];
            *(float2*)&out[o1] = p1;
        }
    }
}

// ---------------------------------------------------------------------------
extern "C" void kernel_launch(void* const* d_in, const int* in_sizes, int n_in,
                              void* d_out, int out_size)
{
    const float* x    = (const float*)d_in[0];
    const float* edge = (const float*)d_in[1];
    const float* fw1  = (const float*)d_in[2];
    const float* fb1  = (const float*)d_in[3];
    const float* fw2  = (const float*)d_in[4];
    const float* fb2  = (const float*)d_in[5];
    const float* gw1  = (const float*)d_in[6];
    const float* gb1  = (const float*)d_in[7];
    const float* gw2  = (const float*)d_in[8];
    const float* gb2  = (const float*)d_in[9];
    float* out = (float*)d_out;

    const int SMEM1 = (2*W_PS + 2*A0_PS + 2*A1_PS) * 2;     // 88064 B
    const int SMEM2 = (2*2*SE_PS + 2*2*SG_PS) * 2;          // 53248 B

    cudaFuncSetAttribute(stage1_kernel, cudaFuncAttributeMaxDynamicSharedMemorySize, SMEM1);
    cudaFuncSetAttribute(stage2_kernel, cudaFuncAttributeMaxDynamicSharedMemorySize, SMEM2);

    stage1_kernel<<<512, 256, SMEM1>>>(x, fw1, fb1, fw2, fb2, gw1, gb1, gw2, gb2, out);
    stage2_kernel<<<dim3(32, NB), 256, SMEM2>>>(edge, out);
}

// round 6
// speedup vs baseline: 2.4131x; 1.1453x over previous
#include <cuda_runtime.h>
#include <cuda_bf16.h>
#include <stdint.h>

#define NB   8
#define MM   2048
#define DIN  64
#define DH   128
#define NODES (NB*MM)
#define KSPLIT 2

// scratch for gx as split bf16 (hi + lo), layout [n][i][h]
__device__ __align__(16) __nv_bfloat16 g_ghi[NODES * DH];
__device__ __align__(16) __nv_bfloat16 g_glo[NODES * DH];
// stage2 partial accumulator for K-half 1
__device__ __align__(16) float g_part[NODES * DH];

// prepped split-bf16 weights, smem-identical layout [64][W_LDT]
#define W_LDT  136
__device__ __align__(16) __nv_bfloat16 pw_hi[5][64 * W_LDT];
__device__ __align__(16) __nv_bfloat16 pw_lo[5][64 * W_LDT];

// ---------------------------------------------------------------------------
#define LDSM_X4(r0,r1,r2,r3,addr) \
    asm volatile("ldmatrix.sync.aligned.m8n8.x4.shared.b16 {%0,%1,%2,%3}, [%4];" \
        : "=r"(r0),"=r"(r1),"=r"(r2),"=r"(r3) : "r"(addr))
#define LDSM_X4_T(r0,r1,r2,r3,addr) \
    asm volatile("ldmatrix.sync.aligned.m8n8.x4.trans.shared.b16 {%0,%1,%2,%3}, [%4];" \
        : "=r"(r0),"=r"(r1),"=r"(r2),"=r"(r3) : "r"(addr))
#define MMA16816(c,a,b) \
    asm volatile("mma.sync.aligned.m16n8k16.row.col.f32.bf16.bf16.f32 " \
        "{%0,%1,%2,%3}, {%4,%5,%6,%7}, {%8,%9}, {%0,%1,%2,%3};" \
        : "+f"(c[0]),"+f"(c[1]),"+f"(c[2]),"+f"(c[3]) \
        : "r"(a[0]),"r"(a[1]),"r"(a[2]),"r"(a[3]),"r"(b[0]),"r"(b[1]))
#define CP_ASYNC16(dst,src) \
    asm volatile("cp.async.cg.shared.global [%0], [%1], 16;" :: "r"(dst), "l"(src))
#define CP_COMMIT() asm volatile("cp.async.commit_group;")
#define CP_WAIT0()  asm volatile("cp.async.wait_group 0;")

__device__ __forceinline__ void split2(float v0, float v1, uint32_t& hi, uint32_t& lo)
{
    __nv_bfloat16 h0 = __float2bfloat16(v0);
    __nv_bfloat16 h1 = __float2bfloat16(v1);
    __nv_bfloat16 l0 = __float2bfloat16(v0 - __bfloat162float(h0));
    __nv_bfloat16 l1 = __float2bfloat16(v1 - __bfloat162float(h1));
    hi = (uint32_t)__bfloat16_as_ushort(h0) | ((uint32_t)__bfloat16_as_ushort(h1) << 16);
    lo = (uint32_t)__bfloat16_as_ushort(l0) | ((uint32_t)__bfloat16_as_ushort(l1) << 16);
}

// ===========================================================================
// Weight prep: fp32 weights -> split-bf16 planes (g_w1 collapsed, g_w2 halved)
// layers: 0=f1(64x64) 1=f2(64x128) 2=g1c(64x128) 3=g2[0:64] 4=g2[64:128]
// ===========================================================================
__global__ void prep_kernel(
    const float* __restrict__ fw1, const float* __restrict__ fw2,
    const float* __restrict__ gw1, const float* __restrict__ gw2)
{
    const int tot = 2048 + 4*4096;   // col-pairs
    for (int idx = blockIdx.x*blockDim.x + threadIdx.x; idx < tot;
         idx += gridDim.x*blockDim.x) {
        int layer, rem, N;
        if (idx < 2048) { layer = 0; rem = idx; N = 64; }
        else { int r = idx - 2048; layer = 1 + (r >> 12); rem = r & 4095; N = 128; }
        int k  = rem / (N/2);
        int n2 = (rem - k*(N/2)) * 2;
        float v0, v1;
        switch (layer) {
            case 0: v0 = fw1[k*64 + n2];  v1 = fw1[k*64 + n2 + 1];  break;
            case 1: v0 = fw2[k*128 + n2]; v1 = fw2[k*128 + n2 + 1]; break;
            case 2: v0 = gw1[k*128 + n2] + gw1[(k + 64)*128 + n2];
                    v1 = gw1[k*128 + n2 + 1] + gw1[(k + 64)*128 + n2 + 1]; break;
            case 3: v0 = gw2[k*128 + n2]; v1 = gw2[k*128 + n2 + 1]; break;
            default: v0 = gw2[(k + 64)*128 + n2]; v1 = gw2[(k + 64)*128 + n2 + 1]; break;
        }
        uint32_t hi, lo;
        split2(v0, v1, hi, lo);
        *(uint32_t*)&pw_hi[layer][k*W_LDT + n2] = hi;
        *(uint32_t*)&pw_lo[layer][k*W_LDT + n2] = lo;
    }
}

// ===========================================================================
// Stage 1: f-path blocks (0..255) and g-path blocks (256..511), 64 rows each.
// ===========================================================================
#define A0_LDT 72
#define A1_LDT 136
#define W_PS   (64*W_LDT)
#define A0_PS  (64*A0_LDT)
#define A1_PS  (64*A1_LDT)

template<int NFR>
__device__ __forceinline__ void mma_pass(
    float acc[2][NFR][4],
    uint32_t aHiA, uint32_t aLoA, int aLDT, int kColOfs,
    uint32_t wHiA, uint32_t wLoA,
    int lane, int wm, int wn)
{
    const int arow = wm*32 + (lane & 15);
    const int aq   = ((lane >> 4) & 1) * 8;
    const int bq   = ((lane >> 4) & 1) * 8;
    #pragma unroll
    for (int ks = 0; ks < 4; ks++) {
        uint32_t ah[2][4], al[2][4];
        #pragma unroll
        for (int mf = 0; mf < 2; mf++) {
            uint32_t ao = (uint32_t)(((arow + mf*16)*aLDT + kColOfs + ks*16 + aq) * 2);
            LDSM_X4(ah[mf][0], ah[mf][1], ah[mf][2], ah[mf][3], aHiA + ao);
            LDSM_X4(al[mf][0], al[mf][1], al[mf][2], al[mf][3], aLoA + ao);
        }
        uint32_t bh[(NFR+1)/2][4], bl[(NFR+1)/2][4];
        #pragma unroll
        for (int nf2 = 0; nf2 < (NFR+1)/2; nf2++) {
            uint32_t bo = (uint32_t)((((ks*16) + (lane & 15))*W_LDT + wn*NFR*8 + nf2*16 + bq) * 2);
            LDSM_X4_T(bh[nf2][0], bh[nf2][1], bh[nf2][2], bh[nf2][3], wHiA + bo);
            LDSM_X4_T(bl[nf2][0], bl[nf2][1], bl[nf2][2], bl[nf2][3], wLoA + bo);
        }
        #pragma unroll
        for (int mf = 0; mf < 2; mf++)
            #pragma unroll
            for (int nf = 0; nf < NFR; nf++) {
                uint32_t* bhf = &bh[nf>>1][(nf&1)*2];
                uint32_t* blf = &bl[nf>>1][(nf&1)*2];
                MMA16816(acc[mf][nf], ah[mf], bhf);
                MMA16816(acc[mf][nf], ah[mf], blf);
                MMA16816(acc[mf][nf], al[mf], bhf);
            }
    }
}

template<int NFR>
__device__ __forceinline__ void init_bias(float acc[2][NFR][4],
    const float* __restrict__ b, int lane, int wn)
{
    #pragma unroll
    for (int nf = 0; nf < NFR; nf++) {
        int c = wn*NFR*8 + nf*8 + (lane & 3)*2;
        float b0 = b[c], b1 = b[c + 1];
        #pragma unroll
        for (int mf = 0; mf < 2; mf++) {
            acc[mf][nf][0] = b0; acc[mf][nf][1] = b1;
            acc[mf][nf][2] = b0; acc[mf][nf][3] = b1;
        }
    }
}

template<int NFR>
__device__ __forceinline__ void epi_relu_split(float acc[2][NFR][4],
    __nv_bfloat16* dHi, __nv_bfloat16* dLo, int ldt, int lane, int wm, int wn)
{
    #pragma unroll
    for (int mf = 0; mf < 2; mf++) {
        int r0 = wm*32 + mf*16 + (lane >> 2);
        #pragma unroll
        for (int nf = 0; nf < NFR; nf++) {
            int c = wn*NFR*8 + nf*8 + (lane & 3)*2;
            uint32_t hi, lo;
            split2(fmaxf(acc[mf][nf][0], 0.f), fmaxf(acc[mf][nf][1], 0.f), hi, lo);
            *(uint32_t*)&dHi[r0*ldt + c] = hi;
            *(uint32_t*)&dLo[r0*ldt + c] = lo;
            split2(fmaxf(acc[mf][nf][2], 0.f), fmaxf(acc[mf][nf][3], 0.f), hi, lo);
            *(uint32_t*)&dHi[(r0 + 8)*ldt + c] = hi;
            *(uint32_t*)&dLo[(r0 + 8)*ldt + c] = lo;
        }
    }
}

// pure 16B async copy of prepped weight planes into smem
__device__ __forceinline__ void load_weight_cp(int layer,
    uint32_t wHiA, uint32_t wLoA, int t)
{
    const uint8_t* srcH = (const uint8_t*)pw_hi[layer];
    const uint8_t* srcL = (const uint8_t*)pw_lo[layer];
    for (int idx = t; idx < (64*W_LDT*2)/16; idx += 256) {   // 1088
        CP_ASYNC16(wHiA + idx*16, srcH + idx*16);
        CP_ASYNC16(wLoA + idx*16, srcL + idx*16);
    }
    CP_COMMIT();
    CP_WAIT0();
}

__global__ __launch_bounds__(256) void stage1_kernel(
    const float* __restrict__ x,
    const float* __restrict__ fb1, const float* __restrict__ fb2,
    const float* __restrict__ gb1, const float* __restrict__ gb2,
    float* __restrict__ out)
{
    extern __shared__ __nv_bfloat16 s1[];
    __nv_bfloat16* wHi  = s1;
    __nv_bfloat16* wLo  = wHi  + W_PS;
    __nv_bfloat16* a0Hi = wLo  + W_PS;
    __nv_bfloat16* a0Lo = a0Hi + A0_PS;
    __nv_bfloat16* a1Hi = a0Lo + A0_PS;
    __nv_bfloat16* a1Lo = a1Hi + A1_PS;

    const int t = threadIdx.x, lane = t & 31, wid = t >> 5;
    const int wm = wid >> 2, wn = wid & 3;
    const bool fpath = (blockIdx.x < 256);
    const int nodeBase = (blockIdx.x & 255) * 64;

    const uint32_t wHiA  = (uint32_t)__cvta_generic_to_shared(wHi);
    const uint32_t wLoA  = (uint32_t)__cvta_generic_to_shared(wLo);
    const uint32_t a0HiA = (uint32_t)__cvta_generic_to_shared(a0Hi);
    const uint32_t a0LoA = (uint32_t)__cvta_generic_to_shared(a0Lo);
    const uint32_t a1HiA = (uint32_t)__cvta_generic_to_shared(a1Hi);
    const uint32_t a1LoA = (uint32_t)__cvta_generic_to_shared(a1Lo);

    // x tile [64 x 64] split
    for (int idx = t; idx < 64*64/2; idx += 256) {
        int r  = idx >> 5;
        int c2 = (idx & 31) * 2;
        float2 v = *(const float2*)&x[(size_t)(nodeBase + r)*DIN + c2];
        uint32_t hi, lo;
        split2(v.x, v.y, hi, lo);
        *(uint32_t*)&a0Hi[r*A0_LDT + c2] = hi;
        *(uint32_t*)&a0Lo[r*A0_LDT + c2] = lo;
    }

    if (fpath) {
        load_weight_cp(0, wHiA, wLoA, t);
        __syncthreads();
        {   // f1
            float acc[2][2][4];
            init_bias<2>(acc, fb1, lane, wn);
            mma_pass<2>(acc, a0HiA, a0LoA, A0_LDT, 0, wHiA, wLoA, lane, wm, wn);
            epi_relu_split<2>(acc, a1Hi, a1Lo, A1_LDT, lane, wm, wn);
        }
        __syncthreads();
        load_weight_cp(1, wHiA, wLoA, t);
        __syncthreads();
        {   // f2 -> out
            float acc[2][4][4];
            init_bias<4>(acc, fb2, lane, wn);
            mma_pass<4>(acc, a1HiA, a1LoA, A1_LDT, 0, wHiA, wLoA, lane, wm, wn);
            #pragma unroll
            for (int mf = 0; mf < 2; mf++) {
                int r0 = nodeBase + wm*32 + mf*16 + (lane >> 2);
                #pragma unroll
                for (int nf = 0; nf < 4; nf++) {
                    int c = wn*32 + nf*8 + (lane & 3)*2;
                    *(float2*)&out[(size_t)r0*DH + c]       = make_float2(acc[mf][nf][0], acc[mf][nf][1]);
                    *(float2*)&out[(size_t)(r0 + 8)*DH + c] = make_float2(acc[mf][nf][2], acc[mf][nf][3]);
                }
            }
        }
    } else {
        load_weight_cp(2, wHiA, wLoA, t);
        __syncthreads();
        {   // g1 (collapsed)
            float acc[2][4][4];
            init_bias<4>(acc, gb1, lane, wn);
            mma_pass<4>(acc, a0HiA, a0LoA, A0_LDT, 0, wHiA, wLoA, lane, wm, wn);
            epi_relu_split<4>(acc, a1Hi, a1Lo, A1_LDT, lane, wm, wn);
        }
        __syncthreads();
        load_weight_cp(3, wHiA, wLoA, t);
        __syncthreads();
        float acc[2][4][4];
        init_bias<4>(acc, gb2, lane, wn);
        mma_pass<4>(acc, a1HiA, a1LoA, A1_LDT, 0, wHiA, wLoA, lane, wm, wn);
        __syncthreads();
        load_weight_cp(4, wHiA, wLoA, t);
        __syncthreads();
        mma_pass<4>(acc, a1HiA, a1LoA, A1_LDT, 64, wHiA, wLoA, lane, wm, wn);

        // epilogue: split store -> gx planes [n][i][h] (coalesced)
        #pragma unroll
        for (int mf = 0; mf < 2; mf++) {
            int r0 = nodeBase + wm*32 + mf*16 + (lane >> 2);
            #pragma unroll
            for (int nf = 0; nf < 4; nf++) {
                int c = wn*32 + nf*8 + (lane & 3)*2;
                uint32_t hi, lo;
                split2(acc[mf][nf][0], acc[mf][nf][1], hi, lo);
                *(uint32_t*)&g_ghi[(size_t)r0*DH + c] = hi;
                *(uint32_t*)&g_glo[(size_t)r0*DH + c] = lo;
                split2(acc[mf][nf][2], acc[mf][nf][3], hi, lo);
                *(uint32_t*)&g_ghi[(size_t)(r0 + 8)*DH + c] = hi;
                *(uint32_t*)&g_glo[(size_t)(r0 + 8)*DH + c] = lo;
            }
        }
    }
}

// ===========================================================================
// Stage 2: out[n,j,h] += sum_i edge[n,i,j]*gx[n,i,h]; 3-term split-bf16 MMA.
// grid (32, 8, KSPLIT): BM=64 x BN=128, BK=32, double buffer, 1 sync/iter.
// K-half 0 RMW-adds into out (self_dyn base); K-half 1 stores to g_part.
// ===========================================================================
#define BK    32
#define EPAD  72
#define GPAD  136
#define SE_PS (BK*EPAD)
#define SG_PS (BK*GPAD)
#define KITER (MM/(BK*KSPLIT))     // 32

__global__ __launch_bounds__(256) void stage2_kernel(
    const float* __restrict__ edge, float* __restrict__ out)
{
    extern __shared__ __nv_bfloat16 sm2[];
    __nv_bfloat16* sE = sm2;
    __nv_bfloat16* sG = sm2 + 2*2*SE_PS;

    const int n  = blockIdx.y;
    const int j0 = blockIdx.x * 64;
    const int kz = blockIdx.z;
    const int koff = kz * (MM / KSPLIT);
    const int t = threadIdx.x, lane = t & 31, wid = t >> 5;
    const int wm = wid >> 2, wn = wid & 3;

    const float* eg = edge + (size_t)n*MM*MM + j0;
    const __nv_bfloat16* gh = g_ghi + (size_t)n*MM*DH;
    const __nv_bfloat16* gl = g_glo + (size_t)n*MM*DH;

    const uint32_t sEb = (uint32_t)__cvta_generic_to_shared(sE);
    const uint32_t sGb = (uint32_t)__cvta_generic_to_shared(sG);

    const int ldrow = t >> 4;
    const int ecol  = (t & 15) * 4;
    const int gcol  = (t & 15) * 8;

    const int arow_off = ((lane >> 4) & 1)*8 + (lane & 7);
    const int aq1      = ((lane >> 3) & 1)*8;
    const int bq       = ((lane >> 4) & 1)*8;

    float acc[2][4][4];
    #pragma unroll
    for (int a = 0; a < 2; a++)
        #pragma unroll
        for (int b = 0; b < 4; b++)
            #pragma unroll
            for (int c = 0; c < 4; c++) acc[a][b][c] = 0.f;

    float4 er[2];

    // prologue: chunk 0 into buf 0
    #pragma unroll
    for (int u = 0; u < 2; u++) {
        int row = ldrow + u*16;
        CP_ASYNC16(sGb + (uint32_t)(((0*2 + 0)*BK + row)*GPAD + gcol)*2, gh + (size_t)(koff + row)*DH + gcol);
        CP_ASYNC16(sGb + (uint32_t)(((0*2 + 1)*BK + row)*GPAD + gcol)*2, gl + (size_t)(koff + row)*DH + gcol);
    }
    CP_COMMIT();
    #pragma unroll
    for (int u = 0; u < 2; u++)
        er[u] = *(const float4*)&eg[(size_t)(koff + ldrow + u*16)*MM + ecol];
    #pragma unroll
    for (int u = 0; u < 2; u++) {
        int row = ldrow + u*16;
        float4 v = er[u];
        uint32_t h0, l0, h1, l1;
        split2(v.x, v.y, h0, l0);
        split2(v.z, v.w, h1, l1);
        *(uint2*)&sE[((0*2 + 0)*BK + row)*EPAD + ecol] = make_uint2(h0, h1);
        *(uint2*)&sE[((0*2 + 1)*BK + row)*EPAD + ecol] = make_uint2(l0, l1);
    }
    CP_WAIT0();

    for (int kt = 0; kt < KITER; kt++) {
        const int buf = kt & 1;
        __syncthreads();

        if (kt + 1 < KITER) {
            const int i0 = koff + (kt + 1) * BK;
            #pragma unroll
            for (int u = 0; u < 2; u++) {
                int row = ldrow + u*16;
                CP_ASYNC16(sGb + (uint32_t)((((buf^1)*2 + 0)*BK + row)*GPAD + gcol)*2,
                           gh + (size_t)(i0 + row)*DH + gcol);
                CP_ASYNC16(sGb + (uint32_t)((((buf^1)*2 + 1)*BK + row)*GPAD + gcol)*2,
                           gl + (size_t)(i0 + row)*DH + gcol);
            }
            CP_COMMIT();
            #pragma unroll
            for (int u = 0; u < 2; u++)
                er[u] = *(const float4*)&eg[(size_t)(i0 + ldrow + u*16)*MM + ecol];
        }

        #pragma unroll
        for (int ks = 0; ks < BK; ks += 16) {
            uint32_t ah[2][4], al[2][4];
            #pragma unroll
            for (int mf = 0; mf < 2; mf++) {
                int acol = wm*32 + mf*16 + aq1;
                uint32_t a0 = sEb + (uint32_t)((((buf*2 + 0)*BK + ks + arow_off)*EPAD + acol)*2);
                uint32_t a1 = sEb + (uint32_t)((((buf*2 + 1)*BK + ks + arow_off)*EPAD + acol)*2);
                LDSM_X4_T(ah[mf][0], ah[mf][1], ah[mf][2], ah[mf][3], a0);
                LDSM_X4_T(al[mf][0], al[mf][1], al[mf][2], al[mf][3], a1);
            }
            uint32_t bh[2][4], bl[2][4];
            #pragma unroll
            for (int nf2 = 0; nf2 < 2; nf2++) {
                int bcol = wn*32 + nf2*16 + bq;
                uint32_t b0 = sGb + (uint32_t)((((buf*2 + 0)*BK + ks + (lane & 15))*GPAD + bcol)*2);
                uint32_t b1 = sGb + (uint32_t)((((buf*2 + 1)*BK + ks + (lane & 15))*GPAD + bcol)*2);
                LDSM_X4_T(bh[nf2][0], bh[nf2][1], bh[nf2][2], bh[nf2][3], b0);
                LDSM_X4_T(bl[nf2][0], bl[nf2][1], bl[nf2][2], bl[nf2][3], b1);
            }
            #pragma unroll
            for (int mf = 0; mf < 2; mf++)
                #pragma unroll
                for (int nf = 0; nf < 4; nf++) {
                    uint32_t* bhf = &bh[nf>>1][(nf&1)*2];
                    uint32_t* blf = &bl[nf>>1][(nf&1)*2];
                    MMA16816(acc[mf][nf], ah[mf], bhf);
                    MMA16816(acc[mf][nf], ah[mf], blf);
                    MMA16816(acc[mf][nf], al[mf], bhf);
                }
        }

        if (kt + 1 < KITER) {
            #pragma unroll
            for (int u = 0; u < 2; u++) {
                int row = ldrow + u*16;
                float4 v = er[u];
                uint32_t h0, l0, h1, l1;
                split2(v.x, v.y, h0, l0);
                split2(v.z, v.w, h1, l1);
                *(uint2*)&sE[(((buf^1)*2 + 0)*BK + row)*EPAD + ecol] = make_uint2(h0, h1);
                *(uint2*)&sE[(((buf^1)*2 + 1)*BK + row)*EPAD + ecol] = make_uint2(l0, l1);
            }
        }
        CP_WAIT0();
    }

    // epilogue
    #pragma unroll
    for (int mf = 0; mf < 2; mf++) {
        int r0 = j0 + wm*32 + mf*16 + (lane >> 2);
        #pragma unroll
        for (int nf = 0; nf < 4; nf++) {
            int c = wn*32 + nf*8 + (lane & 3)*2;
            size_t o0 = ((size_t)n*MM + r0)*DH + c;
            size_t o1 = o0 + (size_t)8*DH;
            if (kz == 0) {
                float2 p0 = *(float2*)&out[o0];
                p0.x += acc[mf][nf][0]; p0.y += acc[mf][nf][1];
                *(float2*)&out[o0] = p0;
                float2 p1 = *(float2*)&out[o1];
                p1.x += acc[mf][nf][2]; p1.y += acc[mf][nf][3];
                *(float2*)&out[o1] = p1;
            } else {
                *(float2*)&g_part[o0] = make_float2(acc[mf][nf][0], acc[mf][nf][1]);
                *(float2*)&g_part[o1] = make_float2(acc[mf][nf][2], acc[mf][nf][3]);
            }
        }
    }
}

// ===========================================================================
// final reduce: out += g_part
// ===========================================================================
__global__ void reduce_kernel(float* __restrict__ out)
{
    int idx = blockIdx.x*blockDim.x + threadIdx.x;
    const int tot4 = NODES*DH/4;
    for (int i = idx; i < tot4; i += gridDim.x*blockDim.x) {
        float4 a = ((float4*)out)[i];
        float4 b = ((const float4*)g_part)[i];
        a.x += b.x; a.y += b.y; a.z += b.z; a.w += b.w;
        ((float4*)out)[i] = a;
    }
}

// ---------------------------------------------------------------------------
extern "C" void kernel_launch(void* const* d_in, const int* in_sizes, int n_in,
                              void* d_out, int out_size)
{
    const float* x    = (const float*)d_in[0];
    const float* edge = (const float*)d_in[1];
    const float* fw1  = (const float*)d_in[2];
    const float* fb1  = (const float*)d_in[3];
    const float* fw2  = (const float*)d_in[4];
    const float* fb2  = (const float*)d_in[5];
    const float* gw1  = (const float*)d_in[6];
    const float* gb1  = (const float*)d_in[7];
    const float* gw2  = (const float*)d_in[8];
    const float* gb2  = (const float*)d_in[9];
    float* out = (float*)d_out;

    const int SMEM1 = (2*W_PS + 2*A0_PS + 2*A1_PS) * 2;   // 88064 B
    const int SMEM2 = (2*2*SE_PS + 2*2*SG_PS) * 2;        // 53248 B

    cudaFuncSetAttribute(stage1_kernel, cudaFuncAttributeMaxDynamicSharedMemorySize, SMEM1);
    cudaFuncSetAttribute(stage2_kernel, cudaFuncAttributeMaxDynamicSharedMemorySize, SMEM2);

    prep_kernel<<<72, 256>>>(fw1, fw2, gw1, gw2);
    stage1_kernel<<<512, 256, SMEM1>>>(x, fb1, fb2, gb1, gb2, out);
    stage2_kernel<<<dim3(32, NB, KSPLIT), 256, SMEM2>>>(edge, out);
    reduce_kernel<<<512, 256>>>(out);
}

// round 7
// speedup vs baseline: 3.0248x; 1.2535x over previous
#include <cuda_runtime.h>
#include <cuda_bf16.h>
#include <cuda_fp16.h>
#include <stdint.h>

#define NB   8
#define MM   2048
#define DIN  64
#define DH   128
#define NODES (NB*MM)
#define KSPLIT 2

// scratch for gx as split fp16 (hi + lo), layout [n][i][h]
__device__ __align__(16) __half g_ghi[NODES * DH];
__device__ __align__(16) __half g_glo[NODES * DH];
// stage2 partial accumulator for K-half 1
__device__ __align__(16) float g_part[NODES * DH];

// prepped split-bf16 weights for stage1, smem-identical layout [64][W_LDT]
#define W_LDT  136
__device__ __align__(16) __nv_bfloat16 pw_hi[5][64 * W_LDT];
__device__ __align__(16) __nv_bfloat16 pw_lo[5][64 * W_LDT];

// ---------------------------------------------------------------------------
#define LDSM_X4(r0,r1,r2,r3,addr) \
    asm volatile("ldmatrix.sync.aligned.m8n8.x4.shared.b16 {%0,%1,%2,%3}, [%4];" \
        : "=r"(r0),"=r"(r1),"=r"(r2),"=r"(r3) : "r"(addr))
#define LDSM_X4_T(r0,r1,r2,r3,addr) \
    asm volatile("ldmatrix.sync.aligned.m8n8.x4.trans.shared.b16 {%0,%1,%2,%3}, [%4];" \
        : "=r"(r0),"=r"(r1),"=r"(r2),"=r"(r3) : "r"(addr))
#define MMA16816(c,a,b) \
    asm volatile("mma.sync.aligned.m16n8k16.row.col.f32.bf16.bf16.f32 " \
        "{%0,%1,%2,%3}, {%4,%5,%6,%7}, {%8,%9}, {%0,%1,%2,%3};" \
        : "+f"(c[0]),"+f"(c[1]),"+f"(c[2]),"+f"(c[3]) \
        : "r"(a[0]),"r"(a[1]),"r"(a[2]),"r"(a[3]),"r"(b[0]),"r"(b[1]))
#define MMAF16(c,a,b) \
    asm volatile("mma.sync.aligned.m16n8k16.row.col.f32.f16.f16.f32 " \
        "{%0,%1,%2,%3}, {%4,%5,%6,%7}, {%8,%9}, {%0,%1,%2,%3};" \
        : "+f"(c[0]),"+f"(c[1]),"+f"(c[2]),"+f"(c[3]) \
        : "r"(a[0]),"r"(a[1]),"r"(a[2]),"r"(a[3]),"r"(b[0]),"r"(b[1]))
#define CP_ASYNC16(dst,src) \
    asm volatile("cp.async.cg.shared.global [%0], [%1], 16;" :: "r"(dst), "l"(src))
#define CP_COMMIT() asm volatile("cp.async.commit_group;")
#define CP_WAIT0()  asm volatile("cp.async.wait_group 0;")

__device__ __forceinline__ void split2(float v0, float v1, uint32_t& hi, uint32_t& lo)
{
    __nv_bfloat16 h0 = __float2bfloat16(v0);
    __nv_bfloat16 h1 = __float2bfloat16(v1);
    __nv_bfloat16 l0 = __float2bfloat16(v0 - __bfloat162float(h0));
    __nv_bfloat16 l1 = __float2bfloat16(v1 - __bfloat162float(h1));
    hi = (uint32_t)__bfloat16_as_ushort(h0) | ((uint32_t)__bfloat16_as_ushort(h1) << 16);
    lo = (uint32_t)__bfloat16_as_ushort(l0) | ((uint32_t)__bfloat16_as_ushort(l1) << 16);
}

// fp16 exact-ish split: v = hi + lo with hi,lo fp16
__device__ __forceinline__ void split2h(float v0, float v1, uint32_t& hi, uint32_t& lo)
{
    __half h0 = __float2half_rn(v0);
    __half h1 = __float2half_rn(v1);
    __half l0 = __float2half_rn(v0 - __half2float(h0));
    __half l1 = __float2half_rn(v1 - __half2float(h1));
    hi = (uint32_t)__half_as_ushort(h0) | ((uint32_t)__half_as_ushort(h1) << 16);
    lo = (uint32_t)__half_as_ushort(l0) | ((uint32_t)__half_as_ushort(l1) << 16);
}

__device__ __forceinline__ uint32_t pack_h2(float a, float b)
{
    __half2 h = __floats2half2_rn(a, b);
    return *(uint32_t*)&h;
}

// ===========================================================================
// Weight prep: fp32 weights -> split-bf16 planes (g_w1 collapsed, g_w2 halved)
// layers: 0=f1(64x64) 1=f2(64x128) 2=g1c(64x128) 3=g2[0:64] 4=g2[64:128]
// ===========================================================================
__global__ void prep_kernel(
    const float* __restrict__ fw1, const float* __restrict__ fw2,
    const float* __restrict__ gw1, const float* __restrict__ gw2)
{
    const int tot = 2048 + 4*4096;   // col-pairs
    for (int idx = blockIdx.x*blockDim.x + threadIdx.x; idx < tot;
         idx += gridDim.x*blockDim.x) {
        int layer, rem, N;
        if (idx < 2048) { layer = 0; rem = idx; N = 64; }
        else { int r = idx - 2048; layer = 1 + (r >> 12); rem = r & 4095; N = 128; }
        int k  = rem / (N/2);
        int n2 = (rem - k*(N/2)) * 2;
        float v0, v1;
        switch (layer) {
            case 0: v0 = fw1[k*64 + n2];  v1 = fw1[k*64 + n2 + 1];  break;
            case 1: v0 = fw2[k*128 + n2]; v1 = fw2[k*128 + n2 + 1]; break;
            case 2: v0 = gw1[k*128 + n2] + gw1[(k + 64)*128 + n2];
                    v1 = gw1[k*128 + n2 + 1] + gw1[(k + 64)*128 + n2 + 1]; break;
            case 3: v0 = gw2[k*128 + n2]; v1 = gw2[k*128 + n2 + 1]; break;
            default: v0 = gw2[(k + 64)*128 + n2]; v1 = gw2[(k + 64)*128 + n2 + 1]; break;
        }
        uint32_t hi, lo;
        split2(v0, v1, hi, lo);
        *(uint32_t*)&pw_hi[layer][k*W_LDT + n2] = hi;
        *(uint32_t*)&pw_lo[layer][k*W_LDT + n2] = lo;
    }
}

// ===========================================================================
// Stage 1: f-path blocks (0..255) and g-path blocks (256..511), 64 rows each.
// ===========================================================================
#define A0_LDT 72
#define A1_LDT 136
#define W_PS   (64*W_LDT)
#define A0_PS  (64*A0_LDT)
#define A1_PS  (64*A1_LDT)

template<int NFR>
__device__ __forceinline__ void mma_pass(
    float acc[2][NFR][4],
    uint32_t aHiA, uint32_t aLoA, int aLDT, int kColOfs,
    uint32_t wHiA, uint32_t wLoA,
    int lane, int wm, int wn)
{
    const int arow = wm*32 + (lane & 15);
    const int aq   = ((lane >> 4) & 1) * 8;
    const int bq   = ((lane >> 4) & 1) * 8;
    #pragma unroll
    for (int ks = 0; ks < 4; ks++) {
        uint32_t ah[2][4], al[2][4];
        #pragma unroll
        for (int mf = 0; mf < 2; mf++) {
            uint32_t ao = (uint32_t)(((arow + mf*16)*aLDT + kColOfs + ks*16 + aq) * 2);
            LDSM_X4(ah[mf][0], ah[mf][1], ah[mf][2], ah[mf][3], aHiA + ao);
            LDSM_X4(al[mf][0], al[mf][1], al[mf][2], al[mf][3], aLoA + ao);
        }
        uint32_t bh[(NFR+1)/2][4], bl[(NFR+1)/2][4];
        #pragma unroll
        for (int nf2 = 0; nf2 < (NFR+1)/2; nf2++) {
            uint32_t bo = (uint32_t)((((ks*16) + (lane & 15))*W_LDT + wn*NFR*8 + nf2*16 + bq) * 2);
            LDSM_X4_T(bh[nf2][0], bh[nf2][1], bh[nf2][2], bh[nf2][3], wHiA + bo);
            LDSM_X4_T(bl[nf2][0], bl[nf2][1], bl[nf2][2], bl[nf2][3], wLoA + bo);
        }
        #pragma unroll
        for (int mf = 0; mf < 2; mf++)
            #pragma unroll
            for (int nf = 0; nf < NFR; nf++) {
                uint32_t* bhf = &bh[nf>>1][(nf&1)*2];
                uint32_t* blf = &bl[nf>>1][(nf&1)*2];
                MMA16816(acc[mf][nf], ah[mf], bhf);
                MMA16816(acc[mf][nf], ah[mf], blf);
                MMA16816(acc[mf][nf], al[mf], bhf);
            }
    }
}

template<int NFR>
__device__ __forceinline__ void init_bias(float acc[2][NFR][4],
    const float* __restrict__ b, int lane, int wn)
{
    #pragma unroll
    for (int nf = 0; nf < NFR; nf++) {
        int c = wn*NFR*8 + nf*8 + (lane & 3)*2;
        float b0 = b[c], b1 = b[c + 1];
        #pragma unroll
        for (int mf = 0; mf < 2; mf++) {
            acc[mf][nf][0] = b0; acc[mf][nf][1] = b1;
            acc[mf][nf][2] = b0; acc[mf][nf][3] = b1;
        }
    }
}

template<int NFR>
__device__ __forceinline__ void epi_relu_split(float acc[2][NFR][4],
    __nv_bfloat16* dHi, __nv_bfloat16* dLo, int ldt, int lane, int wm, int wn)
{
    #pragma unroll
    for (int mf = 0; mf < 2; mf++) {
        int r0 = wm*32 + mf*16 + (lane >> 2);
        #pragma unroll
        for (int nf = 0; nf < NFR; nf++) {
            int c = wn*NFR*8 + nf*8 + (lane & 3)*2;
            uint32_t hi, lo;
            split2(fmaxf(acc[mf][nf][0], 0.f), fmaxf(acc[mf][nf][1], 0.f), hi, lo);
            *(uint32_t*)&dHi[r0*ldt + c] = hi;
            *(uint32_t*)&dLo[r0*ldt + c] = lo;
            split2(fmaxf(acc[mf][nf][2], 0.f), fmaxf(acc[mf][nf][3], 0.f), hi, lo);
            *(uint32_t*)&dHi[(r0 + 8)*ldt + c] = hi;
            *(uint32_t*)&dLo[(r0 + 8)*ldt + c] = lo;
        }
    }
}

// pure 16B async copy of prepped weight planes into smem
__device__ __forceinline__ void load_weight_cp(int layer,
    uint32_t wHiA, uint32_t wLoA, int t)
{
    const uint8_t* srcH = (const uint8_t*)pw_hi[layer];
    const uint8_t* srcL = (const uint8_t*)pw_lo[layer];
    for (int idx = t; idx < (64*W_LDT*2)/16; idx += 256) {   // 1088
        CP_ASYNC16(wHiA + idx*16, srcH + idx*16);
        CP_ASYNC16(wLoA + idx*16, srcL + idx*16);
    }
    CP_COMMIT();
    CP_WAIT0();
}

__global__ __launch_bounds__(256) void stage1_kernel(
    const float* __restrict__ x,
    const float* __restrict__ fb1, const float* __restrict__ fb2,
    const float* __restrict__ gb1, const float* __restrict__ gb2,
    float* __restrict__ out)
{
    extern __shared__ __nv_bfloat16 s1[];
    __nv_bfloat16* wHi  = s1;
    __nv_bfloat16* wLo  = wHi  + W_PS;
    __nv_bfloat16* a0Hi = wLo  + W_PS;
    __nv_bfloat16* a0Lo = a0Hi + A0_PS;
    __nv_bfloat16* a1Hi = a0Lo + A0_PS;
    __nv_bfloat16* a1Lo = a1Hi + A1_PS;

    const int t = threadIdx.x, lane = t & 31, wid = t >> 5;
    const int wm = wid >> 2, wn = wid & 3;
    const bool fpath = (blockIdx.x < 256);
    const int nodeBase = (blockIdx.x & 255) * 64;

    const uint32_t wHiA  = (uint32_t)__cvta_generic_to_shared(wHi);
    const uint32_t wLoA  = (uint32_t)__cvta_generic_to_shared(wLo);
    const uint32_t a0HiA = (uint32_t)__cvta_generic_to_shared(a0Hi);
    const uint32_t a0LoA = (uint32_t)__cvta_generic_to_shared(a0Lo);
    const uint32_t a1HiA = (uint32_t)__cvta_generic_to_shared(a1Hi);
    const uint32_t a1LoA = (uint32_t)__cvta_generic_to_shared(a1Lo);

    // x tile [64 x 64] split
    for (int idx = t; idx < 64*64/2; idx += 256) {
        int r  = idx >> 5;
        int c2 = (idx & 31) * 2;
        float2 v = *(const float2*)&x[(size_t)(nodeBase + r)*DIN + c2];
        uint32_t hi, lo;
        split2(v.x, v.y, hi, lo);
        *(uint32_t*)&a0Hi[r*A0_LDT + c2] = hi;
        *(uint32_t*)&a0Lo[r*A0_LDT + c2] = lo;
    }

    if (fpath) {
        load_weight_cp(0, wHiA, wLoA, t);
        __syncthreads();
        {   // f1
            float acc[2][2][4];
            init_bias<2>(acc, fb1, lane, wn);
            mma_pass<2>(acc, a0HiA, a0LoA, A0_LDT, 0, wHiA, wLoA, lane, wm, wn);
            epi_relu_split<2>(acc, a1Hi, a1Lo, A1_LDT, lane, wm, wn);
        }
        __syncthreads();
        load_weight_cp(1, wHiA, wLoA, t);
        __syncthreads();
        {   // f2 -> out
            float acc[2][4][4];
            init_bias<4>(acc, fb2, lane, wn);
            mma_pass<4>(acc, a1HiA, a1LoA, A1_LDT, 0, wHiA, wLoA, lane, wm, wn);
            #pragma unroll
            for (int mf = 0; mf < 2; mf++) {
                int r0 = nodeBase + wm*32 + mf*16 + (lane >> 2);
                #pragma unroll
                for (int nf = 0; nf < 4; nf++) {
                    int c = wn*32 + nf*8 + (lane & 3)*2;
                    *(float2*)&out[(size_t)r0*DH + c]       = make_float2(acc[mf][nf][0], acc[mf][nf][1]);
                    *(float2*)&out[(size_t)(r0 + 8)*DH + c] = make_float2(acc[mf][nf][2], acc[mf][nf][3]);
                }
            }
        }
    } else {
        load_weight_cp(2, wHiA, wLoA, t);
        __syncthreads();
        {   // g1 (collapsed)
            float acc[2][4][4];
            init_bias<4>(acc, gb1, lane, wn);
            mma_pass<4>(acc, a0HiA, a0LoA, A0_LDT, 0, wHiA, wLoA, lane, wm, wn);
            epi_relu_split<4>(acc, a1Hi, a1Lo, A1_LDT, lane, wm, wn);
        }
        __syncthreads();
        load_weight_cp(3, wHiA, wLoA, t);
        __syncthreads();
        float acc[2][4][4];
        init_bias<4>(acc, gb2, lane, wn);
        mma_pass<4>(acc, a1HiA, a1LoA, A1_LDT, 0, wHiA, wLoA, lane, wm, wn);
        __syncthreads();
        load_weight_cp(4, wHiA, wLoA, t);
        __syncthreads();
        mma_pass<4>(acc, a1HiA, a1LoA, A1_LDT, 64, wHiA, wLoA, lane, wm, wn);

        // epilogue: fp16 split store -> gx planes [n][i][h] (coalesced)
        #pragma unroll
        for (int mf = 0; mf < 2; mf++) {
            int r0 = nodeBase + wm*32 + mf*16 + (lane >> 2);
            #pragma unroll
            for (int nf = 0; nf < 4; nf++) {
                int c = wn*32 + nf*8 + (lane & 3)*2;
                uint32_t hi, lo;
                split2h(acc[mf][nf][0], acc[mf][nf][1], hi, lo);
                *(uint32_t*)&g_ghi[(size_t)r0*DH + c] = hi;
                *(uint32_t*)&g_glo[(size_t)r0*DH + c] = lo;
                split2h(acc[mf][nf][2], acc[mf][nf][3], hi, lo);
                *(uint32_t*)&g_ghi[(size_t)(r0 + 8)*DH + c] = hi;
                *(uint32_t*)&g_glo[(size_t)(r0 + 8)*DH + c] = lo;
            }
        }
    }
}

// ===========================================================================
// Stage 2 (fp16 2-term): out[n,j,h] += sum_i edge[n,i,j]*gx[n,i,h]
// E as single fp16 plane; G as fp16 hi+lo. C += Eh*Gh + Eh*Gl.
// grid (32, 8, KSPLIT): BM=64 x BN=128, BK=32, double buffer, 1 sync/iter.
// ===========================================================================
#define BK    32
#define EPAD  72
#define GPAD  136
#define SE_PS (BK*EPAD)
#define SG_PS (BK*GPAD)
#define KITER (MM/(BK*KSPLIT))     // 32

__global__ __launch_bounds__(256) void stage2_kernel(
    const float* __restrict__ edge, float* __restrict__ out)
{
    extern __shared__ __half sm2[];
    __half* sE = sm2;                   // [2 buf][BK][EPAD]
    __half* sG = sm2 + 2*SE_PS;         // [2 buf][2 pl][BK][GPAD]

    const int n  = blockIdx.y;
    const int j0 = blockIdx.x * 64;
    const int kz = blockIdx.z;
    const int koff = kz * (MM / KSPLIT);
    const int t = threadIdx.x, lane = t & 31, wid = t >> 5;
    const int wm = wid >> 2, wn = wid & 3;

    const float* eg = edge + (size_t)n*MM*MM + j0;
    const __half* gh = g_ghi + (size_t)n*MM*DH;
    const __half* gl = g_glo + (size_t)n*MM*DH;

    const uint32_t sEb = (uint32_t)__cvta_generic_to_shared(sE);
    const uint32_t sGb = (uint32_t)__cvta_generic_to_shared(sG);

    const int ldrow = t >> 4;          // 0..15 (and +16)
    const int ecol  = (t & 15) * 4;
    const int gcol  = (t & 15) * 8;

    const int arow_off = ((lane >> 4) & 1)*8 + (lane & 7);
    const int aq1      = ((lane >> 3) & 1)*8;
    const int bq       = ((lane >> 4) & 1)*8;

    float acc[2][4][4];
    #pragma unroll
    for (int a = 0; a < 2; a++)
        #pragma unroll
        for (int b = 0; b < 4; b++)
            #pragma unroll
            for (int c = 0; c < 4; c++) acc[a][b][c] = 0.f;

    float4 er[2];

    // prologue: chunk 0 into buf 0
    #pragma unroll
    for (int u = 0; u < 2; u++) {
        int row = ldrow + u*16;
        CP_ASYNC16(sGb + (uint32_t)(((0*2 + 0)*BK + row)*GPAD + gcol)*2, gh + (size_t)(koff + row)*DH + gcol);
        CP_ASYNC16(sGb + (uint32_t)(((0*2 + 1)*BK + row)*GPAD + gcol)*2, gl + (size_t)(koff + row)*DH + gcol);
    }
    CP_COMMIT();
    #pragma unroll
    for (int u = 0; u < 2; u++)
        er[u] = *(const float4*)&eg[(size_t)(koff + ldrow + u*16)*MM + ecol];
    #pragma unroll
    for (int u = 0; u < 2; u++) {
        int row = ldrow + u*16;
        float4 v = er[u];
        *(uint2*)&sE[(0*BK + row)*EPAD + ecol] =
            make_uint2(pack_h2(v.x, v.y), pack_h2(v.z, v.w));
    }
    CP_WAIT0();

    for (int kt = 0; kt < KITER; kt++) {
        const int buf = kt & 1;
        __syncthreads();

        if (kt + 1 < KITER) {
            const int i0 = koff + (kt + 1) * BK;
            #pragma unroll
            for (int u = 0; u < 2; u++) {
                int row = ldrow + u*16;
                CP_ASYNC16(sGb + (uint32_t)((((buf^1)*2 + 0)*BK + row)*GPAD + gcol)*2,
                           gh + (size_t)(i0 + row)*DH + gcol);
                CP_ASYNC16(sGb + (uint32_t)((((buf^1)*2 + 1)*BK + row)*GPAD + gcol)*2,
                           gl + (size_t)(i0 + row)*DH + gcol);
            }
            CP_COMMIT();
            #pragma unroll
            for (int u = 0; u < 2; u++)
                er[u] = *(const float4*)&eg[(size_t)(i0 + ldrow + u*16)*MM + ecol];
        }

        #pragma unroll
        for (int ks = 0; ks < BK; ks += 16) {
            uint32_t ah[2][4];
            #pragma unroll
            for (int mf = 0; mf < 2; mf++) {
                int acol = wm*32 + mf*16 + aq1;
                uint32_t a0 = sEb + (uint32_t)(((buf*BK + ks + arow_off)*EPAD + acol)*2);
                LDSM_X4_T(ah[mf][0], ah[mf][1], ah[mf][2], ah[mf][3], a0);
            }
            uint32_t bh[2][4], bl[2][4];
            #pragma unroll
            for (int nf2 = 0; nf2 < 2; nf2++) {
                int bcol = wn*32 + nf2*16 + bq;
                uint32_t b0 = sGb + (uint32_t)((((buf*2 + 0)*BK + ks + (lane & 15))*GPAD + bcol)*2);
                uint32_t b1 = sGb + (uint32_t)((((buf*2 + 1)*BK + ks + (lane & 15))*GPAD + bcol)*2);
                LDSM_X4_T(bh[nf2][0], bh[nf2][1], bh[nf2][2], bh[nf2][3], b0);
                LDSM_X4_T(bl[nf2][0], bl[nf2][1], bl[nf2][2], bl[nf2][3], b1);
            }
            #pragma unroll
            for (int mf = 0; mf < 2; mf++)
                #pragma unroll
                for (int nf = 0; nf < 4; nf++) {
                    uint32_t* bhf = &bh[nf>>1][(nf&1)*2];
                    uint32_t* blf = &bl[nf>>1][(nf&1)*2];
                    MMAF16(acc[mf][nf], ah[mf], bhf);
                    MMAF16(acc[mf][nf], ah[mf], blf);
                }
        }

        if (kt + 1 < KITER) {
            #pragma unroll
            for (int u = 0; u < 2; u++) {
                int row = ldrow + u*16;
                float4 v = er[u];
                *(uint2*)&sE[((buf^1)*BK + row)*EPAD + ecol] =
                    make_uint2(pack_h2(v.x, v.y), pack_h2(v.z, v.w));
            }
        }
        CP_WAIT0();
    }

    // epilogue
    #pragma unroll
    for (int mf = 0; mf < 2; mf++) {
        int r0 = j0 + wm*32 + mf*16 + (lane >> 2);
        #pragma unroll
        for (int nf = 0; nf < 4; nf++) {
            int c = wn*32 + nf*8 + (lane & 3)*2;
            size_t o0 = ((size_t)n*MM + r0)*DH + c;
            size_t o1 = o0 + (size_t)8*DH;
            if (kz == 0) {
                float2 p0 = *(float2*)&out[o0];
                p0.x += acc[mf][nf][0]; p0.y += acc[mf][nf][1];
                *(float2*)&out[o0] = p0;
                float2 p1 = *(float2*)&out[o1];
                p1.x += acc[mf][nf][2]; p1.y += acc[mf][nf][3];
                *(float2*)&out[o1] = p1;
            } else {
                *(float2*)&g_part[o0] = make_float2(acc[mf][nf][0], acc[mf][nf][1]);
                *(float2*)&g_part[o1] = make_float2(acc[mf][nf][2], acc[mf][nf][3]);
            }
        }
    }
}

// ===========================================================================
// final reduce: out += g_part
// ===========================================================================
__global__ void reduce_kernel(float* __restrict__ out)
{
    int idx = blockIdx.x*blockDim.x + threadIdx.x;
    const int tot4 = NODES*DH/4;
    for (int i = idx; i < tot4; i += gridDim.x*blockDim.x) {
        float4 a = ((float4*)out)[i];
        float4 b = ((const float4*)g_part)[i];
        a.x += b.x; a.y += b.y; a.z += b.z; a.w += b.w;
        ((float4*)out)[i] = a;
    }
}

// ---------------------------------------------------------------------------
extern "C" void kernel_launch(void* const* d_in, const int* in_sizes, int n_in,
                              void* d_out, int out_size)
{
    const float* x    = (const float*)d_in[0];
    const float* edge = (const float*)d_in[1];
    const float* fw1  = (const float*)d_in[2];
    const float* fb1  = (const float*)d_in[3];
    const float* fw2  = (const float*)d_in[4];
    const float* fb2  = (const float*)d_in[5];
    const float* gw1  = (const float*)d_in[6];
    const float* gb1  = (const float*)d_in[7];
    const float* gw2  = (const float*)d_in[8];
    const float* gb2  = (const float*)d_in[9];
    float* out = (float*)d_out;

    const int SMEM1 = (2*W_PS + 2*A0_PS + 2*A1_PS) * 2;   // 88064 B
    const int SMEM2 = (2*SE_PS + 2*2*SG_PS) * 2;          // 44032 B

    cudaFuncSetAttribute(stage1_kernel, cudaFuncAttributeMaxDynamicSharedMemorySize, SMEM1);
    cudaFuncSetAttribute(stage2_kernel, cudaFuncAttributeMaxDynamicSharedMemorySize, SMEM2);

    prep_kernel<<<72, 256>>>(fw1, fw2, gw1, gw2);
    stage1_kernel<<<512, 256, SMEM1>>>(x, fb1, fb2, gb1, gb2, out);
    stage2_kernel<<<dim3(32, NB, KSPLIT), 256, SMEM2>>>(edge, out);
    reduce_kernel<<<512, 256>>>(out);
}

// round 8
// speedup vs baseline: 3.3907x; 1.1210x over previous
#include <cuda_runtime.h>
#include <cuda_bf16.h>
#include <cuda_fp16.h>
#include <stdint.h>

#define NB   8
#define MM   2048
#define DIN  64
#define DH   128
#define NODES (NB*MM)
#define KSPLIT 2

// scratch for gx as fp16, layout [n][i][h]
__device__ __align__(16) __half g_gh[NODES * DH];

// prepped split-bf16 weights for stage1, smem-identical layout [64][W_LDT]
#define W_LDT  136
__device__ __align__(16) __nv_bfloat16 pw_hi[5][64 * W_LDT];
__device__ __align__(16) __nv_bfloat16 pw_lo[5][64 * W_LDT];

// ---------------------------------------------------------------------------
#define LDSM_X4(r0,r1,r2,r3,addr) \
    asm volatile("ldmatrix.sync.aligned.m8n8.x4.shared.b16 {%0,%1,%2,%3}, [%4];" \
        : "=r"(r0),"=r"(r1),"=r"(r2),"=r"(r3) : "r"(addr))
#define LDSM_X4_T(r0,r1,r2,r3,addr) \
    asm volatile("ldmatrix.sync.aligned.m8n8.x4.trans.shared.b16 {%0,%1,%2,%3}, [%4];" \
        : "=r"(r0),"=r"(r1),"=r"(r2),"=r"(r3) : "r"(addr))
#define MMA16816(c,a,b) \
    asm volatile("mma.sync.aligned.m16n8k16.row.col.f32.bf16.bf16.f32 " \
        "{%0,%1,%2,%3}, {%4,%5,%6,%7}, {%8,%9}, {%0,%1,%2,%3};" \
        : "+f"(c[0]),"+f"(c[1]),"+f"(c[2]),"+f"(c[3]) \
        : "r"(a[0]),"r"(a[1]),"r"(a[2]),"r"(a[3]),"r"(b[0]),"r"(b[1]))
#define MMAF16(c,a,b) \
    asm volatile("mma.sync.aligned.m16n8k16.row.col.f32.f16.f16.f32 " \
        "{%0,%1,%2,%3}, {%4,%5,%6,%7}, {%8,%9}, {%0,%1,%2,%3};" \
        : "+f"(c[0]),"+f"(c[1]),"+f"(c[2]),"+f"(c[3]) \
        : "r"(a[0]),"r"(a[1]),"r"(a[2]),"r"(a[3]),"r"(b[0]),"r"(b[1]))
#define CP_ASYNC16(dst,src) \
    asm volatile("cp.async.cg.shared.global [%0], [%1], 16;" :: "r"(dst), "l"(src))
#define CP_COMMIT() asm volatile("cp.async.commit_group;")
#define CP_WAIT0()  asm volatile("cp.async.wait_group 0;")

__device__ __forceinline__ void split2(float v0, float v1, uint32_t& hi, uint32_t& lo)
{
    __nv_bfloat16 h0 = __float2bfloat16(v0);
    __nv_bfloat16 h1 = __float2bfloat16(v1);
    __nv_bfloat16 l0 = __float2bfloat16(v0 - __bfloat162float(h0));
    __nv_bfloat16 l1 = __float2bfloat16(v1 - __bfloat162float(h1));
    hi = (uint32_t)__bfloat16_as_ushort(h0) | ((uint32_t)__bfloat16_as_ushort(h1) << 16);
    lo = (uint32_t)__bfloat16_as_ushort(l0) | ((uint32_t)__bfloat16_as_ushort(l1) << 16);
}

__device__ __forceinline__ uint32_t pack_h2(float a, float b)
{
    __half2 h = __floats2half2_rn(a, b);
    return *(uint32_t*)&h;
}

// ===========================================================================
// Weight prep: fp32 weights -> split-bf16 planes (g_w1 collapsed, g_w2 halved)
// layers: 0=f1(64x64) 1=f2(64x128) 2=g1c(64x128) 3=g2[0:64] 4=g2[64:128]
// ===========================================================================
__global__ void prep_kernel(
    const float* __restrict__ fw1, const float* __restrict__ fw2,
    const float* __restrict__ gw1, const float* __restrict__ gw2)
{
    const int tot = 2048 + 4*4096;   // col-pairs
    for (int idx = blockIdx.x*blockDim.x + threadIdx.x; idx < tot;
         idx += gridDim.x*blockDim.x) {
        int layer, rem, N;
        if (idx < 2048) { layer = 0; rem = idx; N = 64; }
        else { int r = idx - 2048; layer = 1 + (r >> 12); rem = r & 4095; N = 128; }
        int k  = rem / (N/2);
        int n2 = (rem - k*(N/2)) * 2;
        float v0, v1;
        switch (layer) {
            case 0: v0 = fw1[k*64 + n2];  v1 = fw1[k*64 + n2 + 1];  break;
            case 1: v0 = fw2[k*128 + n2]; v1 = fw2[k*128 + n2 + 1]; break;
            case 2: v0 = gw1[k*128 + n2] + gw1[(k + 64)*128 + n2];
                    v1 = gw1[k*128 + n2 + 1] + gw1[(k + 64)*128 + n2 + 1]; break;
            case 3: v0 = gw2[k*128 + n2]; v1 = gw2[k*128 + n2 + 1]; break;
            default: v0 = gw2[(k + 64)*128 + n2]; v1 = gw2[(k + 64)*128 + n2 + 1]; break;
        }
        uint32_t hi, lo;
        split2(v0, v1, hi, lo);
        *(uint32_t*)&pw_hi[layer][k*W_LDT + n2] = hi;
        *(uint32_t*)&pw_lo[layer][k*W_LDT + n2] = lo;
    }
}

// ===========================================================================
// Stage 1: f-path blocks (0..255) and g-path blocks (256..511), 64 rows each.
// ===========================================================================
#define A0_LDT 72
#define A1_LDT 136
#define W_PS   (64*W_LDT)
#define A0_PS  (64*A0_LDT)
#define A1_PS  (64*A1_LDT)

template<int NFR>
__device__ __forceinline__ void mma_pass(
    float acc[2][NFR][4],
    uint32_t aHiA, uint32_t aLoA, int aLDT, int kColOfs,
    uint32_t wHiA, uint32_t wLoA,
    int lane, int wm, int wn)
{
    const int arow = wm*32 + (lane & 15);
    const int aq   = ((lane >> 4) & 1) * 8;
    const int bq   = ((lane >> 4) & 1) * 8;
    #pragma unroll
    for (int ks = 0; ks < 4; ks++) {
        uint32_t ah[2][4], al[2][4];
        #pragma unroll
        for (int mf = 0; mf < 2; mf++) {
            uint32_t ao = (uint32_t)(((arow + mf*16)*aLDT + kColOfs + ks*16 + aq) * 2);
            LDSM_X4(ah[mf][0], ah[mf][1], ah[mf][2], ah[mf][3], aHiA + ao);
            LDSM_X4(al[mf][0], al[mf][1], al[mf][2], al[mf][3], aLoA + ao);
        }
        uint32_t bh[(NFR+1)/2][4], bl[(NFR+1)/2][4];
        #pragma unroll
        for (int nf2 = 0; nf2 < (NFR+1)/2; nf2++) {
            uint32_t bo = (uint32_t)((((ks*16) + (lane & 15))*W_LDT + wn*NFR*8 + nf2*16 + bq) * 2);
            LDSM_X4_T(bh[nf2][0], bh[nf2][1], bh[nf2][2], bh[nf2][3], wHiA + bo);
            LDSM_X4_T(bl[nf2][0], bl[nf2][1], bl[nf2][2], bl[nf2][3], wLoA + bo);
        }
        #pragma unroll
        for (int mf = 0; mf < 2; mf++)
            #pragma unroll
            for (int nf = 0; nf < NFR; nf++) {
                uint32_t* bhf = &bh[nf>>1][(nf&1)*2];
                uint32_t* blf = &bl[nf>>1][(nf&1)*2];
                MMA16816(acc[mf][nf], ah[mf], bhf);
                MMA16816(acc[mf][nf], ah[mf], blf);
                MMA16816(acc[mf][nf], al[mf], bhf);
            }
    }
}

template<int NFR>
__device__ __forceinline__ void init_bias(float acc[2][NFR][4],
    const float* __restrict__ b, int lane, int wn)
{
    #pragma unroll
    for (int nf = 0; nf < NFR; nf++) {
        int c = wn*NFR*8 + nf*8 + (lane & 3)*2;
        float b0 = b[c], b1 = b[c + 1];
        #pragma unroll
        for (int mf = 0; mf < 2; mf++) {
            acc[mf][nf][0] = b0; acc[mf][nf][1] = b1;
            acc[mf][nf][2] = b0; acc[mf][nf][3] = b1;
        }
    }
}

template<int NFR>
__device__ __forceinline__ void epi_relu_split(float acc[2][NFR][4],
    __nv_bfloat16* dHi, __nv_bfloat16* dLo, int ldt, int lane, int wm, int wn)
{
    #pragma unroll
    for (int mf = 0; mf < 2; mf++) {
        int r0 = wm*32 + mf*16 + (lane >> 2);
        #pragma unroll
        for (int nf = 0; nf < NFR; nf++) {
            int c = wn*NFR*8 + nf*8 + (lane & 3)*2;
            uint32_t hi, lo;
            split2(fmaxf(acc[mf][nf][0], 0.f), fmaxf(acc[mf][nf][1], 0.f), hi, lo);
            *(uint32_t*)&dHi[r0*ldt + c] = hi;
            *(uint32_t*)&dLo[r0*ldt + c] = lo;
            split2(fmaxf(acc[mf][nf][2], 0.f), fmaxf(acc[mf][nf][3], 0.f), hi, lo);
            *(uint32_t*)&dHi[(r0 + 8)*ldt + c] = hi;
            *(uint32_t*)&dLo[(r0 + 8)*ldt + c] = lo;
        }
    }
}

// pure 16B async copy of prepped weight planes into smem
__device__ __forceinline__ void load_weight_cp(int layer,
    uint32_t wHiA, uint32_t wLoA, int t)
{
    const uint8_t* srcH = (const uint8_t*)pw_hi[layer];
    const uint8_t* srcL = (const uint8_t*)pw_lo[layer];
    for (int idx = t; idx < (64*W_LDT*2)/16; idx += 256) {   // 1088
        CP_ASYNC16(wHiA + idx*16, srcH + idx*16);
        CP_ASYNC16(wLoA + idx*16, srcL + idx*16);
    }
    CP_COMMIT();
    CP_WAIT0();
}

__global__ __launch_bounds__(256) void stage1_kernel(
    const float* __restrict__ x,
    const float* __restrict__ fb1, const float* __restrict__ fb2,
    const float* __restrict__ gb1, const float* __restrict__ gb2,
    float* __restrict__ out)
{
    extern __shared__ __nv_bfloat16 s1[];
    __nv_bfloat16* wHi  = s1;
    __nv_bfloat16* wLo  = wHi  + W_PS;
    __nv_bfloat16* a0Hi = wLo  + W_PS;
    __nv_bfloat16* a0Lo = a0Hi + A0_PS;
    __nv_bfloat16* a1Hi = a0Lo + A0_PS;
    __nv_bfloat16* a1Lo = a1Hi + A1_PS;

    const int t = threadIdx.x, lane = t & 31, wid = t >> 5;
    const int wm = wid >> 2, wn = wid & 3;
    const bool fpath = (blockIdx.x < 256);
    const int nodeBase = (blockIdx.x & 255) * 64;

    const uint32_t wHiA  = (uint32_t)__cvta_generic_to_shared(wHi);
    const uint32_t wLoA  = (uint32_t)__cvta_generic_to_shared(wLo);
    const uint32_t a0HiA = (uint32_t)__cvta_generic_to_shared(a0Hi);
    const uint32_t a0LoA = (uint32_t)__cvta_generic_to_shared(a0Lo);
    const uint32_t a1HiA = (uint32_t)__cvta_generic_to_shared(a1Hi);
    const uint32_t a1LoA = (uint32_t)__cvta_generic_to_shared(a1Lo);

    // x tile [64 x 64] split
    for (int idx = t; idx < 64*64/2; idx += 256) {
        int r  = idx >> 5;
        int c2 = (idx & 31) * 2;
        float2 v = *(const float2*)&x[(size_t)(nodeBase + r)*DIN + c2];
        uint32_t hi, lo;
        split2(v.x, v.y, hi, lo);
        *(uint32_t*)&a0Hi[r*A0_LDT + c2] = hi;
        *(uint32_t*)&a0Lo[r*A0_LDT + c2] = lo;
    }

    if (fpath) {
        load_weight_cp(0, wHiA, wLoA, t);
        __syncthreads();
        {   // f1
            float acc[2][2][4];
            init_bias<2>(acc, fb1, lane, wn);
            mma_pass<2>(acc, a0HiA, a0LoA, A0_LDT, 0, wHiA, wLoA, lane, wm, wn);
            epi_relu_split<2>(acc, a1Hi, a1Lo, A1_LDT, lane, wm, wn);
        }
        __syncthreads();
        load_weight_cp(1, wHiA, wLoA, t);
        __syncthreads();
        {   // f2 -> out
            float acc[2][4][4];
            init_bias<4>(acc, fb2, lane, wn);
            mma_pass<4>(acc, a1HiA, a1LoA, A1_LDT, 0, wHiA, wLoA, lane, wm, wn);
            #pragma unroll
            for (int mf = 0; mf < 2; mf++) {
                int r0 = nodeBase + wm*32 + mf*16 + (lane >> 2);
                #pragma unroll
                for (int nf = 0; nf < 4; nf++) {
                    int c = wn*32 + nf*8 + (lane & 3)*2;
                    *(float2*)&out[(size_t)r0*DH + c]       = make_float2(acc[mf][nf][0], acc[mf][nf][1]);
                    *(float2*)&out[(size_t)(r0 + 8)*DH + c] = make_float2(acc[mf][nf][2], acc[mf][nf][3]);
                }
            }
        }
    } else {
        load_weight_cp(2, wHiA, wLoA, t);
        __syncthreads();
        {   // g1 (collapsed)
            float acc[2][4][4];
            init_bias<4>(acc, gb1, lane, wn);
            mma_pass<4>(acc, a0HiA, a0LoA, A0_LDT, 0, wHiA, wLoA, lane, wm, wn);
            epi_relu_split<4>(acc, a1Hi, a1Lo, A1_LDT, lane, wm, wn);
        }
        __syncthreads();
        load_weight_cp(3, wHiA, wLoA, t);
        __syncthreads();
        float acc[2][4][4];
        init_bias<4>(acc, gb2, lane, wn);
        mma_pass<4>(acc, a1HiA, a1LoA, A1_LDT, 0, wHiA, wLoA, lane, wm, wn);
        __syncthreads();
        load_weight_cp(4, wHiA, wLoA, t);
        __syncthreads();
        mma_pass<4>(acc, a1HiA, a1LoA, A1_LDT, 64, wHiA, wLoA, lane, wm, wn);

        // epilogue: single fp16 plane -> g_gh [n][i][h] (coalesced)
        #pragma unroll
        for (int mf = 0; mf < 2; mf++) {
            int r0 = nodeBase + wm*32 + mf*16 + (lane >> 2);
            #pragma unroll
            for (int nf = 0; nf < 4; nf++) {
                int c = wn*32 + nf*8 + (lane & 3)*2;
                *(uint32_t*)&g_gh[(size_t)r0*DH + c] =
                    pack_h2(acc[mf][nf][0], acc[mf][nf][1]);
                *(uint32_t*)&g_gh[(size_t)(r0 + 8)*DH + c] =
                    pack_h2(acc[mf][nf][2], acc[mf][nf][3]);
            }
        }
    }
}

// ===========================================================================
// Stage 2 (pure fp16 1-term): out[n,j,h] += sum_i edge[n,i,j]*gx[n,i,h]
// grid (32, 8, KSPLIT): BM=64 x BN=128, BK=32, double buffer, 1 sync/iter.
// Epilogue: atomicAdd into out from both K-halves (RED.ADD, commutative).
// ===========================================================================
#define BK    32
#define EPAD  72
#define GPAD  136
#define SE_PS (BK*EPAD)
#define SG_PS (BK*GPAD)
#define KITER (MM/(BK*KSPLIT))     // 32

__global__ __launch_bounds__(256) void stage2_kernel(
    const float* __restrict__ edge, float* __restrict__ out)
{
    extern __shared__ __half sm2[];
    __half* sE = sm2;                   // [2 buf][BK][EPAD]
    __half* sG = sm2 + 2*SE_PS;         // [2 buf][BK][GPAD]

    const int n  = blockIdx.y;
    const int j0 = blockIdx.x * 64;
    const int kz = blockIdx.z;
    const int koff = kz * (MM / KSPLIT);
    const int t = threadIdx.x, lane = t & 31, wid = t >> 5;
    const int wm = wid >> 2, wn = wid & 3;

    const float* eg = edge + (size_t)n*MM*MM + j0;
    const __half* gh = g_gh + (size_t)n*MM*DH;

    const uint32_t sEb = (uint32_t)__cvta_generic_to_shared(sE);
    const uint32_t sGb = (uint32_t)__cvta_generic_to_shared(sG);

    const int ldrow = t >> 4;          // 0..15 (and +16)
    const int ecol  = (t & 15) * 4;
    const int gcol  = (t & 15) * 8;

    const int arow_off = ((lane >> 4) & 1)*8 + (lane & 7);
    const int aq1      = ((lane >> 3) & 1)*8;
    const int bq       = ((lane >> 4) & 1)*8;

    float acc[2][4][4];
    #pragma unroll
    for (int a = 0; a < 2; a++)
        #pragma unroll
        for (int b = 0; b < 4; b++)
            #pragma unroll
            for (int c = 0; c < 4; c++) acc[a][b][c] = 0.f;

    float4 er[2];

    // prologue: chunk 0 into buf 0
    #pragma unroll
    for (int u = 0; u < 2; u++) {
        int row = ldrow + u*16;
        CP_ASYNC16(sGb + (uint32_t)((0*BK + row)*GPAD + gcol)*2, gh + (size_t)(koff + row)*DH + gcol);
    }
    CP_COMMIT();
    #pragma unroll
    for (int u = 0; u < 2; u++)
        er[u] = *(const float4*)&eg[(size_t)(koff + ldrow + u*16)*MM + ecol];
    #pragma unroll
    for (int u = 0; u < 2; u++) {
        int row = ldrow + u*16;
        float4 v = er[u];
        *(uint2*)&sE[(0*BK + row)*EPAD + ecol] =
            make_uint2(pack_h2(v.x, v.y), pack_h2(v.z, v.w));
    }
    CP_WAIT0();

    for (int kt = 0; kt < KITER; kt++) {
        const int buf = kt & 1;
        __syncthreads();

        if (kt + 1 < KITER) {
            const int i0 = koff + (kt + 1) * BK;
            #pragma unroll
            for (int u = 0; u < 2; u++) {
                int row = ldrow + u*16;
                CP_ASYNC16(sGb + (uint32_t)(((buf^1)*BK + row)*GPAD + gcol)*2,
                           gh + (size_t)(i0 + row)*DH + gcol);
            }
            CP_COMMIT();
            #pragma unroll
            for (int u = 0; u < 2; u++)
                er[u] = *(const float4*)&eg[(size_t)(i0 + ldrow + u*16)*MM + ecol];
        }

        #pragma unroll
        for (int ks = 0; ks < BK; ks += 16) {
            uint32_t ah[2][4];
            #pragma unroll
            for (int mf = 0; mf < 2; mf++) {
                int acol = wm*32 + mf*16 + aq1;
                uint32_t a0 = sEb + (uint32_t)(((buf*BK + ks + arow_off)*EPAD + acol)*2);
                LDSM_X4_T(ah[mf][0], ah[mf][1], ah[mf][2], ah[mf][3], a0);
            }
            uint32_t bh[2][4];
            #pragma unroll
            for (int nf2 = 0; nf2 < 2; nf2++) {
                int bcol = wn*32 + nf2*16 + bq;
                uint32_t b0 = sGb + (uint32_t)(((buf*BK + ks + (lane & 15))*GPAD + bcol)*2);
                LDSM_X4_T(bh[nf2][0], bh[nf2][1], bh[nf2][2], bh[nf2][3], b0);
            }
            #pragma unroll
            for (int mf = 0; mf < 2; mf++)
                #pragma unroll
                for (int nf = 0; nf < 4; nf++) {
                    uint32_t* bhf = &bh[nf>>1][(nf&1)*2];
                    MMAF16(acc[mf][nf], ah[mf], bhf);
                }
        }

        if (kt + 1 < KITER) {
            #pragma unroll
            for (int u = 0; u < 2; u++) {
                int row = ldrow + u*16;
                float4 v = er[u];
                *(uint2*)&sE[((buf^1)*BK + row)*EPAD + ecol] =
                    make_uint2(pack_h2(v.x, v.y), pack_h2(v.z, v.w));
            }
        }
        CP_WAIT0();
    }

    // epilogue: atomic add into out (commutative across K-halves)
    #pragma unroll
    for (int mf = 0; mf < 2; mf++) {
        int r0 = j0 + wm*32 + mf*16 + (lane >> 2);
        #pragma unroll
        for (int nf = 0; nf < 4; nf++) {
            int c = wn*32 + nf*8 + (lane & 3)*2;
            size_t o0 = ((size_t)n*MM + r0)*DH + c;
            size_t o1 = o0 + (size_t)8*DH;
            atomicAdd(&out[o0],     acc[mf][nf][0]);
            atomicAdd(&out[o0 + 1], acc[mf][nf][1]);
            atomicAdd(&out[o1],     acc[mf][nf][2]);
            atomicAdd(&out[o1 + 1], acc[mf][nf][3]);
        }
    }
}

// ---------------------------------------------------------------------------
extern "C" void kernel_launch(void* const* d_in, const int* in_sizes, int n_in,
                              void* d_out, int out_size)
{
    const float* x    = (const float*)d_in[0];
    const float* edge = (const float*)d_in[1];
    const float* fw1  = (const float*)d_in[2];
    const float* fb1  = (const float*)d_in[3];
    const float* fw2  = (const float*)d_in[4];
    const float* fb2  = (const float*)d_in[5];
    const float* gw1  = (const float*)d_in[6];
    const float* gb1  = (const float*)d_in[7];
    const float* gw2  = (const float*)d_in[8];
    const float* gb2  = (const float*)d_in[9];
    float* out = (float*)d_out;

    const int SMEM1 = (2*W_PS + 2*A0_PS + 2*A1_PS) * 2;   // 88064 B
    const int SMEM2 = (2*SE_PS + 2*SG_PS) * 2;            // 26624 B

    cudaFuncSetAttribute(stage1_kernel, cudaFuncAttributeMaxDynamicSharedMemorySize, SMEM1);
    cudaFuncSetAttribute(stage2_kernel, cudaFuncAttributeMaxDynamicSharedMemorySize, SMEM2);

    prep_kernel<<<72, 256>>>(fw1, fw2, gw1, gw2);
    stage1_kernel<<<512, 256, SMEM1>>>(x, fb1, fb2, gb1, gb2, out);
    stage2_kernel<<<dim3(32, NB, KSPLIT), 256, SMEM2>>>(edge, out);
}

// round 9
// speedup vs baseline: 3.4611x; 1.0208x over previous
#include <cuda_runtime.h>
#include <cuda_bf16.h>
#include <cuda_fp16.h>
#include <stdint.h>

#define NB   8
#define MM   2048
#define DIN  64
#define DH   128
#define NODES (NB*MM)
#define KSPLIT 4

// scratch for gx as fp16, layout [n][i][h]
__device__ __align__(16) __half g_gh[NODES * DH];

// prepped split-bf16 weights for stage1, smem-identical layout [64][W_LDT]
#define W_LDT  136
__device__ __align__(16) __nv_bfloat16 pw_hi[5][64 * W_LDT];
__device__ __align__(16) __nv_bfloat16 pw_lo[5][64 * W_LDT];

// ---------------------------------------------------------------------------
#define LDSM_X4(r0,r1,r2,r3,addr) \
    asm volatile("ldmatrix.sync.aligned.m8n8.x4.shared.b16 {%0,%1,%2,%3}, [%4];" \
        : "=r"(r0),"=r"(r1),"=r"(r2),"=r"(r3) : "r"(addr))
#define LDSM_X4_T(r0,r1,r2,r3,addr) \
    asm volatile("ldmatrix.sync.aligned.m8n8.x4.trans.shared.b16 {%0,%1,%2,%3}, [%4];" \
        : "=r"(r0),"=r"(r1),"=r"(r2),"=r"(r3) : "r"(addr))
#define MMA16816(c,a,b) \
    asm volatile("mma.sync.aligned.m16n8k16.row.col.f32.bf16.bf16.f32 " \
        "{%0,%1,%2,%3}, {%4,%5,%6,%7}, {%8,%9}, {%0,%1,%2,%3};" \
        : "+f"(c[0]),"+f"(c[1]),"+f"(c[2]),"+f"(c[3]) \
        : "r"(a[0]),"r"(a[1]),"r"(a[2]),"r"(a[3]),"r"(b[0]),"r"(b[1]))
#define MMAF16(c,a,b) \
    asm volatile("mma.sync.aligned.m16n8k16.row.col.f32.f16.f16.f32 " \
        "{%0,%1,%2,%3}, {%4,%5,%6,%7}, {%8,%9}, {%0,%1,%2,%3};" \
        : "+f"(c[0]),"+f"(c[1]),"+f"(c[2]),"+f"(c[3]) \
        : "r"(a[0]),"r"(a[1]),"r"(a[2]),"r"(a[3]),"r"(b[0]),"r"(b[1]))
#define CP_ASYNC16(dst,src) \
    asm volatile("cp.async.cg.shared.global [%0], [%1], 16;" :: "r"(dst), "l"(src))
#define CP_COMMIT() asm volatile("cp.async.commit_group;")
#define CP_WAIT0()  asm volatile("cp.async.wait_group 0;")

__device__ __forceinline__ void split2(float v0, float v1, uint32_t& hi, uint32_t& lo)
{
    __nv_bfloat16 h0 = __float2bfloat16(v0);
    __nv_bfloat16 h1 = __float2bfloat16(v1);
    __nv_bfloat16 l0 = __float2bfloat16(v0 - __bfloat162float(h0));
    __nv_bfloat16 l1 = __float2bfloat16(v1 - __bfloat162float(h1));
    hi = (uint32_t)__bfloat16_as_ushort(h0) | ((uint32_t)__bfloat16_as_ushort(h1) << 16);
    lo = (uint32_t)__bfloat16_as_ushort(l0) | ((uint32_t)__bfloat16_as_ushort(l1) << 16);
}

__device__ __forceinline__ uint32_t pack_h2(float a, float b)
{
    __half2 h = __floats2half2_rn(a, b);
    return *(uint32_t*)&h;
}

// ===========================================================================
// Weight prep: fp32 weights -> split-bf16 planes (g_w1 collapsed, g_w2 halved)
// layers: 0=f1(64x64) 1=f2(64x128) 2=g1c(64x128) 3=g2[0:64] 4=g2[64:128]
// ===========================================================================
__global__ void prep_kernel(
    const float* __restrict__ fw1, const float* __restrict__ fw2,
    const float* __restrict__ gw1, const float* __restrict__ gw2)
{
    const int tot = 2048 + 4*4096;   // col-pairs
    for (int idx = blockIdx.x*blockDim.x + threadIdx.x; idx < tot;
         idx += gridDim.x*blockDim.x) {
        int layer, rem, N;
        if (idx < 2048) { layer = 0; rem = idx; N = 64; }
        else { int r = idx - 2048; layer = 1 + (r >> 12); rem = r & 4095; N = 128; }
        int k  = rem / (N/2);
        int n2 = (rem - k*(N/2)) * 2;
        float v0, v1;
        switch (layer) {
            case 0: v0 = fw1[k*64 + n2];  v1 = fw1[k*64 + n2 + 1];  break;
            case 1: v0 = fw2[k*128 + n2]; v1 = fw2[k*128 + n2 + 1]; break;
            case 2: v0 = gw1[k*128 + n2] + gw1[(k + 64)*128 + n2];
                    v1 = gw1[k*128 + n2 + 1] + gw1[(k + 64)*128 + n2 + 1]; break;
            case 3: v0 = gw2[k*128 + n2]; v1 = gw2[k*128 + n2 + 1]; break;
            default: v0 = gw2[(k + 64)*128 + n2]; v1 = gw2[(k + 64)*128 + n2 + 1]; break;
        }
        uint32_t hi, lo;
        split2(v0, v1, hi, lo);
        *(uint32_t*)&pw_hi[layer][k*W_LDT + n2] = hi;
        *(uint32_t*)&pw_lo[layer][k*W_LDT + n2] = lo;
    }
}

// ===========================================================================
// Stage 1: 128-thread blocks, 32 node-rows each.
// f-path blocks (0..511) and g-path blocks (512..1023).
// ===========================================================================
#define S1_T   128
#define S1_R   32
#define A0_LDT 72
#define A1_LDT 136
#define W_PS   (64*W_LDT)
#define A0_PS  (S1_R*A0_LDT)
#define A1_PS  (S1_R*A1_LDT)

template<int NFR>
__device__ __forceinline__ void mma_pass(
    float acc[2][NFR][4],
    uint32_t aHiA, uint32_t aLoA, int aLDT, int kColOfs,
    uint32_t wHiA, uint32_t wLoA,
    int lane, int wn)
{
    const int arow = lane & 15;
    const int aq   = ((lane >> 4) & 1) * 8;
    const int bq   = ((lane >> 4) & 1) * 8;
    #pragma unroll
    for (int ks = 0; ks < 4; ks++) {
        uint32_t ah[2][4], al[2][4];
        #pragma unroll
        for (int mf = 0; mf < 2; mf++) {
            uint32_t ao = (uint32_t)(((arow + mf*16)*aLDT + kColOfs + ks*16 + aq) * 2);
            LDSM_X4(ah[mf][0], ah[mf][1], ah[mf][2], ah[mf][3], aHiA + ao);
            LDSM_X4(al[mf][0], al[mf][1], al[mf][2], al[mf][3], aLoA + ao);
        }
        uint32_t bh[(NFR+1)/2][4], bl[(NFR+1)/2][4];
        #pragma unroll
        for (int nf2 = 0; nf2 < (NFR+1)/2; nf2++) {
            uint32_t bo = (uint32_t)((((ks*16) + (lane & 15))*W_LDT + wn*NFR*8 + nf2*16 + bq) * 2);
            LDSM_X4_T(bh[nf2][0], bh[nf2][1], bh[nf2][2], bh[nf2][3], wHiA + bo);
            LDSM_X4_T(bl[nf2][0], bl[nf2][1], bl[nf2][2], bl[nf2][3], wLoA + bo);
        }
        #pragma unroll
        for (int mf = 0; mf < 2; mf++)
            #pragma unroll
            for (int nf = 0; nf < NFR; nf++) {
                uint32_t* bhf = &bh[nf>>1][(nf&1)*2];
                uint32_t* blf = &bl[nf>>1][(nf&1)*2];
                MMA16816(acc[mf][nf], ah[mf], bhf);
                MMA16816(acc[mf][nf], ah[mf], blf);
                MMA16816(acc[mf][nf], al[mf], bhf);
            }
    }
}

template<int NFR>
__device__ __forceinline__ void init_bias(float acc[2][NFR][4],
    const float* __restrict__ b, int lane, int wn)
{
    #pragma unroll
    for (int nf = 0; nf < NFR; nf++) {
        int c = wn*NFR*8 + nf*8 + (lane & 3)*2;
        float b0 = b[c], b1 = b[c + 1];
        #pragma unroll
        for (int mf = 0; mf < 2; mf++) {
            acc[mf][nf][0] = b0; acc[mf][nf][1] = b1;
            acc[mf][nf][2] = b0; acc[mf][nf][3] = b1;
        }
    }
}

template<int NFR>
__device__ __forceinline__ void epi_relu_split(float acc[2][NFR][4],
    __nv_bfloat16* dHi, __nv_bfloat16* dLo, int ldt, int lane, int wn)
{
    #pragma unroll
    for (int mf = 0; mf < 2; mf++) {
        int r0 = mf*16 + (lane >> 2);
        #pragma unroll
        for (int nf = 0; nf < NFR; nf++) {
            int c = wn*NFR*8 + nf*8 + (lane & 3)*2;
            uint32_t hi, lo;
            split2(fmaxf(acc[mf][nf][0], 0.f), fmaxf(acc[mf][nf][1], 0.f), hi, lo);
            *(uint32_t*)&dHi[r0*ldt + c] = hi;
            *(uint32_t*)&dLo[r0*ldt + c] = lo;
            split2(fmaxf(acc[mf][nf][2], 0.f), fmaxf(acc[mf][nf][3], 0.f), hi, lo);
            *(uint32_t*)&dHi[(r0 + 8)*ldt + c] = hi;
            *(uint32_t*)&dLo[(r0 + 8)*ldt + c] = lo;
        }
    }
}

// pure 16B async copy of prepped weight planes into smem
__device__ __forceinline__ void load_weight_cp(int layer,
    uint32_t wHiA, uint32_t wLoA, int t)
{
    const uint8_t* srcH = (const uint8_t*)pw_hi[layer];
    const uint8_t* srcL = (const uint8_t*)pw_lo[layer];
    for (int idx = t; idx < (64*W_LDT*2)/16; idx += S1_T) {   // 1088
        CP_ASYNC16(wHiA + idx*16, srcH + idx*16);
        CP_ASYNC16(wLoA + idx*16, srcL + idx*16);
    }
    CP_COMMIT();
    CP_WAIT0();
}

__global__ __launch_bounds__(S1_T) void stage1_kernel(
    const float* __restrict__ x,
    const float* __restrict__ fb1, const float* __restrict__ fb2,
    const float* __restrict__ gb1, const float* __restrict__ gb2,
    float* __restrict__ out)
{
    extern __shared__ __nv_bfloat16 s1[];
    __nv_bfloat16* wHi  = s1;
    __nv_bfloat16* wLo  = wHi  + W_PS;
    __nv_bfloat16* a0Hi = wLo  + W_PS;
    __nv_bfloat16* a0Lo = a0Hi + A0_PS;
    __nv_bfloat16* a1Hi = a0Lo + A0_PS;
    __nv_bfloat16* a1Lo = a1Hi + A1_PS;

    const int t = threadIdx.x, lane = t & 31, wid = t >> 5;
    const int wn = wid & 3;
    const bool fpath = (blockIdx.x < 512);
    const int nodeBase = (blockIdx.x & 511) * S1_R;

    const uint32_t wHiA  = (uint32_t)__cvta_generic_to_shared(wHi);
    const uint32_t wLoA  = (uint32_t)__cvta_generic_to_shared(wLo);
    const uint32_t a0HiA = (uint32_t)__cvta_generic_to_shared(a0Hi);
    const uint32_t a0LoA = (uint32_t)__cvta_generic_to_shared(a0Lo);
    const uint32_t a1HiA = (uint32_t)__cvta_generic_to_shared(a1Hi);
    const uint32_t a1LoA = (uint32_t)__cvta_generic_to_shared(a1Lo);

    // x tile [32 x 64] split
    for (int idx = t; idx < S1_R*64/2; idx += S1_T) {
        int r  = idx >> 5;
        int c2 = (idx & 31) * 2;
        float2 v = *(const float2*)&x[(size_t)(nodeBase + r)*DIN + c2];
        uint32_t hi, lo;
        split2(v.x, v.y, hi, lo);
        *(uint32_t*)&a0Hi[r*A0_LDT + c2] = hi;
        *(uint32_t*)&a0Lo[r*A0_LDT + c2] = lo;
    }

    if (fpath) {
        load_weight_cp(0, wHiA, wLoA, t);
        __syncthreads();
        {   // f1
            float acc[2][2][4];
            init_bias<2>(acc, fb1, lane, wn);
            mma_pass<2>(acc, a0HiA, a0LoA, A0_LDT, 0, wHiA, wLoA, lane, wn);
            epi_relu_split<2>(acc, a1Hi, a1Lo, A1_LDT, lane, wn);
        }
        __syncthreads();
        load_weight_cp(1, wHiA, wLoA, t);
        __syncthreads();
        {   // f2 -> out
            float acc[2][4][4];
            init_bias<4>(acc, fb2, lane, wn);
            mma_pass<4>(acc, a1HiA, a1LoA, A1_LDT, 0, wHiA, wLoA, lane, wn);
            #pragma unroll
            for (int mf = 0; mf < 2; mf++) {
                int r0 = nodeBase + mf*16 + (lane >> 2);
                #pragma unroll
                for (int nf = 0; nf < 4; nf++) {
                    int c = wn*32 + nf*8 + (lane & 3)*2;
                    *(float2*)&out[(size_t)r0*DH + c]       = make_float2(acc[mf][nf][0], acc[mf][nf][1]);
                    *(float2*)&out[(size_t)(r0 + 8)*DH + c] = make_float2(acc[mf][nf][2], acc[mf][nf][3]);
                }
            }
        }
    } else {
        load_weight_cp(2, wHiA, wLoA, t);
        __syncthreads();
        {   // g1 (collapsed)
            float acc[2][4][4];
            init_bias<4>(acc, gb1, lane, wn);
            mma_pass<4>(acc, a0HiA, a0LoA, A0_LDT, 0, wHiA, wLoA, lane, wn);
            epi_relu_split<4>(acc, a1Hi, a1Lo, A1_LDT, lane, wn);
        }
        __syncthreads();
        load_weight_cp(3, wHiA, wLoA, t);
        __syncthreads();
        float acc[2][4][4];
        init_bias<4>(acc, gb2, lane, wn);
        mma_pass<4>(acc, a1HiA, a1LoA, A1_LDT, 0, wHiA, wLoA, lane, wn);
        __syncthreads();
        load_weight_cp(4, wHiA, wLoA, t);
        __syncthreads();
        mma_pass<4>(acc, a1HiA, a1LoA, A1_LDT, 64, wHiA, wLoA, lane, wn);

        // epilogue: single fp16 plane -> g_gh [n][i][h] (coalesced)
        #pragma unroll
        for (int mf = 0; mf < 2; mf++) {
            int r0 = nodeBase + mf*16 + (lane >> 2);
            #pragma unroll
            for (int nf = 0; nf < 4; nf++) {
                int c = wn*32 + nf*8 + (lane & 3)*2;
                *(uint32_t*)&g_gh[(size_t)r0*DH + c] =
                    pack_h2(acc[mf][nf][0], acc[mf][nf][1]);
                *(uint32_t*)&g_gh[(size_t)(r0 + 8)*DH + c] =
                    pack_h2(acc[mf][nf][2], acc[mf][nf][3]);
            }
        }
    }
}

// ===========================================================================
// Stage 2 (pure fp16 1-term): out[n,j,h] += sum_i edge[n,i,j]*gx[n,i,h]
// grid (32, 8, KSPLIT=4): BM=64 x BN=128, BK=32, double buffer, 1 sync/iter.
// Epilogue: atomicAdd into out from all K-quarters (RED.ADD, commutative).
// ===========================================================================
#define BK    32
#define EPAD  72
#define GPAD  136
#define SE_PS (BK*EPAD)
#define SG_PS (BK*GPAD)
#define KITER (MM/(BK*KSPLIT))     // 16

__global__ __launch_bounds__(256) void stage2_kernel(
    const float* __restrict__ edge, float* __restrict__ out)
{
    extern __shared__ __half sm2[];
    __half* sE = sm2;                   // [2 buf][BK][EPAD]
    __half* sG = sm2 + 2*SE_PS;         // [2 buf][BK][GPAD]

    const int n  = blockIdx.y;
    const int j0 = blockIdx.x * 64;
    const int kz = blockIdx.z;
    const int koff = kz * (MM / KSPLIT);
    const int t = threadIdx.x, lane = t & 31, wid = t >> 5;
    const int wm = wid >> 2, wn = wid & 3;

    const float* eg = edge + (size_t)n*MM*MM + j0;
    const __half* gh = g_gh + (size_t)n*MM*DH;

    const uint32_t sEb = (uint32_t)__cvta_generic_to_shared(sE);
    const uint32_t sGb = (uint32_t)__cvta_generic_to_shared(sG);

    const int ldrow = t >> 4;          // 0..15 (and +16)
    const int ecol  = (t & 15) * 4;
    const int gcol  = (t & 15) * 8;

    const int arow_off = ((lane >> 4) & 1)*8 + (lane & 7);
    const int aq1      = ((lane >> 3) & 1)*8;
    const int bq       = ((lane >> 4) & 1)*8;

    float acc[2][4][4];
    #pragma unroll
    for (int a = 0; a < 2; a++)
        #pragma unroll
        for (int b = 0; b < 4; b++)
            #pragma unroll
            for (int c = 0; c < 4; c++) acc[a][b][c] = 0.f;

    float4 er[2];

    // prologue: chunk 0 into buf 0
    #pragma unroll
    for (int u = 0; u < 2; u++) {
        int row = ldrow + u*16;
        CP_ASYNC16(sGb + (uint32_t)((0*BK + row)*GPAD + gcol)*2, gh + (size_t)(koff + row)*DH + gcol);
    }
    CP_COMMIT();
    #pragma unroll
    for (int u = 0; u < 2; u++)
        er[u] = *(const float4*)&eg[(size_t)(koff + ldrow + u*16)*MM + ecol];
    #pragma unroll
    for (int u = 0; u < 2; u++) {
        int row = ldrow + u*16;
        float4 v = er[u];
        *(uint2*)&sE[(0*BK + row)*EPAD + ecol] =
            make_uint2(pack_h2(v.x, v.y), pack_h2(v.z, v.w));
    }
    CP_WAIT0();

    for (int kt = 0; kt < KITER; kt++) {
        const int buf = kt & 1;
        __syncthreads();

        if (kt + 1 < KITER) {
            const int i0 = koff + (kt + 1) * BK;
            #pragma unroll
            for (int u = 0; u < 2; u++) {
                int row = ldrow + u*16;
                CP_ASYNC16(sGb + (uint32_t)(((buf^1)*BK + row)*GPAD + gcol)*2,
                           gh + (size_t)(i0 + row)*DH + gcol);
            }
            CP_COMMIT();
            #pragma unroll
            for (int u = 0; u < 2; u++)
                er[u] = *(const float4*)&eg[(size_t)(i0 + ldrow + u*16)*MM + ecol];
        }

        #pragma unroll
        for (int ks = 0; ks < BK; ks += 16) {
            uint32_t ah[2][4];
            #pragma unroll
            for (int mf = 0; mf < 2; mf++) {
                int acol = wm*32 + mf*16 + aq1;
                uint32_t a0 = sEb + (uint32_t)(((buf*BK + ks + arow_off)*EPAD + acol)*2);
                LDSM_X4_T(ah[mf][0], ah[mf][1], ah[mf][2], ah[mf][3], a0);
            }
            uint32_t bh[2][4];
            #pragma unroll
            for (int nf2 = 0; nf2 < 2; nf2++) {
                int bcol = wn*32 + nf2*16 + bq;
                uint32_t b0 = sGb + (uint32_t)(((buf*BK + ks + (lane & 15))*GPAD + bcol)*2);
                LDSM_X4_T(bh[nf2][0], bh[nf2][1], bh[nf2][2], bh[nf2][3], b0);
            }
            #pragma unroll
            for (int mf = 0; mf < 2; mf++)
                #pragma unroll
                for (int nf = 0; nf < 4; nf++) {
                    uint32_t* bhf = &bh[nf>>1][(nf&1)*2];
                    MMAF16(acc[mf][nf], ah[mf], bhf);
                }
        }

        if (kt + 1 < KITER) {
            #pragma unroll
            for (int u = 0; u < 2; u++) {
                int row = ldrow + u*16;
                float4 v = er[u];
                *(uint2*)&sE[((buf^1)*BK + row)*EPAD + ecol] =
                    make_uint2(pack_h2(v.x, v.y), pack_h2(v.z, v.w));
            }
        }
        CP_WAIT0();
    }

    // epilogue: atomic add into out (commutative across K-quarters)
    #pragma unroll
    for (int mf = 0; mf < 2; mf++) {
        int r0 = j0 + wm*32 + mf*16 + (lane >> 2);
        #pragma unroll
        for (int nf = 0; nf < 4; nf++) {
            int c = wn*32 + nf*8 + (lane & 3)*2;
            size_t o0 = ((size_t)n*MM + r0)*DH + c;
            size_t o1 = o0 + (size_t)8*DH;
            atomicAdd(&out[o0],     acc[mf][nf][0]);
            atomicAdd(&out[o0 + 1], acc[mf][nf][1]);
            atomicAdd(&out[o1],     acc[mf][nf][2]);
            atomicAdd(&out[o1 + 1], acc[mf][nf][3]);
        }
    }
}

// ---------------------------------------------------------------------------
extern "C" void kernel_launch(void* const* d_in, const int* in_sizes, int n_in,
                              void* d_out, int out_size)
{
    const float* x    = (const float*)d_in[0];
    const float* edge = (const float*)d_in[1];
    const float* fw1  = (const float*)d_in[2];
    const float* fb1  = (const float*)d_in[3];
    const float* fw2  = (const float*)d_in[4];
    const float* fb2  = (const float*)d_in[5];
    const float* gw1  = (const float*)d_in[6];
    const float* gb1  = (const float*)d_in[7];
    const float* gw2  = (const float*)d_in[8];
    const float* gb2  = (const float*)d_in[9];
    float* out = (float*)d_out;

    const int SMEM1 = (2*W_PS + 2*A0_PS + 2*A1_PS) * 2;   // 61440 B
    const int SMEM2 = (2*SE_PS + 2*SG_PS) * 2;            // 26624 B

    cudaFuncSetAttribute(stage1_kernel, cudaFuncAttributeMaxDynamicSharedMemorySize, SMEM1);
    cudaFuncSetAttribute(stage2_kernel, cudaFuncAttributeMaxDynamicSharedMemorySize, SMEM2);

    prep_kernel<<<72, 256>>>(fw1, fw2, gw1, gw2);
    stage1_kernel<<<1024, S1_T, SMEM1>>>(x, fb1, fb2, gb1, gb2, out);
    stage2_kernel<<<dim3(32, NB, KSPLIT), 256, SMEM2>>>(edge, out);
}

// round 10
// speedup vs baseline: 3.7439x; 1.0817x over previous
#include <cuda_runtime.h>
#include <cuda_bf16.h>
#include <cuda_fp16.h>
#include <stdint.h>

#define NB   8
#define MM   2048
#define DIN  64
#define DH   128
#define NODES (NB*MM)
#define KSPLIT 4

// scratch for gx as fp16, layout [n][i][h]
__device__ __align__(16) __half g_gh[NODES * DH];

// prepped split-bf16 weights for stage1, smem-identical layout [64][W_LDT]
#define W_LDT  136
__device__ __align__(16) __nv_bfloat16 pw_hi[5][64 * W_LDT];
__device__ __align__(16) __nv_bfloat16 pw_lo[5][64 * W_LDT];

// ---------------------------------------------------------------------------
#define LDSM_X4(r0,r1,r2,r3,addr) \
    asm volatile("ldmatrix.sync.aligned.m8n8.x4.shared.b16 {%0,%1,%2,%3}, [%4];" \
        : "=r"(r0),"=r"(r1),"=r"(r2),"=r"(r3) : "r"(addr))
#define LDSM_X4_T(r0,r1,r2,r3,addr) \
    asm volatile("ldmatrix.sync.aligned.m8n8.x4.trans.shared.b16 {%0,%1,%2,%3}, [%4];" \
        : "=r"(r0),"=r"(r1),"=r"(r2),"=r"(r3) : "r"(addr))
#define MMA16816(c,a,b) \
    asm volatile("mma.sync.aligned.m16n8k16.row.col.f32.bf16.bf16.f32 " \
        "{%0,%1,%2,%3}, {%4,%5,%6,%7}, {%8,%9}, {%0,%1,%2,%3};" \
        : "+f"(c[0]),"+f"(c[1]),"+f"(c[2]),"+f"(c[3]) \
        : "r"(a[0]),"r"(a[1]),"r"(a[2]),"r"(a[3]),"r"(b[0]),"r"(b[1]))
#define MMAF16(c,a,b) \
    asm volatile("mma.sync.aligned.m16n8k16.row.col.f32.f16.f16.f32 " \
        "{%0,%1,%2,%3}, {%4,%5,%6,%7}, {%8,%9}, {%0,%1,%2,%3};" \
        : "+f"(c[0]),"+f"(c[1]),"+f"(c[2]),"+f"(c[3]) \
        : "r"(a[0]),"r"(a[1]),"r"(a[2]),"r"(a[3]),"r"(b[0]),"r"(b[1]))
#define CP_ASYNC16(dst,src) \
    asm volatile("cp.async.cg.shared.global [%0], [%1], 16;" :: "r"(dst), "l"(src))
#define CP_COMMIT() asm volatile("cp.async.commit_group;")
#define CP_WAIT0()  asm volatile("cp.async.wait_group 0;")
#define CP_WAIT1()  asm volatile("cp.async.wait_group 1;")

__device__ __forceinline__ void split2(float v0, float v1, uint32_t& hi, uint32_t& lo)
{
    __nv_bfloat16 h0 = __float2bfloat16(v0);
    __nv_bfloat16 h1 = __float2bfloat16(v1);
    __nv_bfloat16 l0 = __float2bfloat16(v0 - __bfloat162float(h0));
    __nv_bfloat16 l1 = __float2bfloat16(v1 - __bfloat162float(h1));
    hi = (uint32_t)__bfloat16_as_ushort(h0) | ((uint32_t)__bfloat16_as_ushort(h1) << 16);
    lo = (uint32_t)__bfloat16_as_ushort(l0) | ((uint32_t)__bfloat16_as_ushort(l1) << 16);
}

__device__ __forceinline__ uint32_t pack_h2(float a, float b)
{
    __half2 h = __floats2half2_rn(a, b);
    return *(uint32_t*)&h;
}

// ===========================================================================
// Weight prep: fp32 weights -> split-bf16 planes (g_w1 collapsed, g_w2 halved)
// layers: 0=f1(64x64) 1=f2(64x128) 2=g1c(64x128) 3=g2[0:64] 4=g2[64:128]
// ===========================================================================
__global__ void prep_kernel(
    const float* __restrict__ fw1, const float* __restrict__ fw2,
    const float* __restrict__ gw1, const float* __restrict__ gw2)
{
    const int tot = 2048 + 4*4096;   // col-pairs
    for (int idx = blockIdx.x*blockDim.x + threadIdx.x; idx < tot;
         idx += gridDim.x*blockDim.x) {
        int layer, rem, N;
        if (idx < 2048) { layer = 0; rem = idx; N = 64; }
        else { int r = idx - 2048; layer = 1 + (r >> 12); rem = r & 4095; N = 128; }
        int k  = rem / (N/2);
        int n2 = (rem - k*(N/2)) * 2;
        float v0, v1;
        switch (layer) {
            case 0: v0 = fw1[k*64 + n2];  v1 = fw1[k*64 + n2 + 1];  break;
            case 1: v0 = fw2[k*128 + n2]; v1 = fw2[k*128 + n2 + 1]; break;
            case 2: v0 = gw1[k*128 + n2] + gw1[(k + 64)*128 + n2];
                    v1 = gw1[k*128 + n2 + 1] + gw1[(k + 64)*128 + n2 + 1]; break;
            case 3: v0 = gw2[k*128 + n2]; v1 = gw2[k*128 + n2 + 1]; break;
            default: v0 = gw2[(k + 64)*128 + n2]; v1 = gw2[(k + 64)*128 + n2 + 1]; break;
        }
        uint32_t hi, lo;
        split2(v0, v1, hi, lo);
        *(uint32_t*)&pw_hi[layer][k*W_LDT + n2] = hi;
        *(uint32_t*)&pw_lo[layer][k*W_LDT + n2] = lo;
    }
}

// ===========================================================================
// Stage 1: 128-thread blocks, 32 node-rows, double-buffered weights with
// deferred cp.async waits (each wait covered by the previous layer's MMAs).
// f-path blocks (0..511) and g-path blocks (512..1023).
// ===========================================================================
#define S1_T   128
#define S1_R   32
#define A0_LDT 72
#define A1_LDT 136
#define W_PS   (64*W_LDT)
#define A0_PS  (S1_R*A0_LDT)
#define A1_PS  (S1_R*A1_LDT)

template<int NFR>
__device__ __forceinline__ void mma_pass(
    float acc[2][NFR][4],
    uint32_t aHiA, uint32_t aLoA, int aLDT, int kColOfs,
    uint32_t wHiA, uint32_t wLoA,
    int lane, int wn)
{
    const int arow = lane & 15;
    const int aq   = ((lane >> 4) & 1) * 8;
    const int bq   = ((lane >> 4) & 1) * 8;
    #pragma unroll
    for (int ks = 0; ks < 4; ks++) {
        uint32_t ah[2][4], al[2][4];
        #pragma unroll
        for (int mf = 0; mf < 2; mf++) {
            uint32_t ao = (uint32_t)(((arow + mf*16)*aLDT + kColOfs + ks*16 + aq) * 2);
            LDSM_X4(ah[mf][0], ah[mf][1], ah[mf][2], ah[mf][3], aHiA + ao);
            LDSM_X4(al[mf][0], al[mf][1], al[mf][2], al[mf][3], aLoA + ao);
        }
        uint32_t bh[(NFR+1)/2][4], bl[(NFR+1)/2][4];
        #pragma unroll
        for (int nf2 = 0; nf2 < (NFR+1)/2; nf2++) {
            uint32_t bo = (uint32_t)((((ks*16) + (lane & 15))*W_LDT + wn*NFR*8 + nf2*16 + bq) * 2);
            LDSM_X4_T(bh[nf2][0], bh[nf2][1], bh[nf2][2], bh[nf2][3], wHiA + bo);
            LDSM_X4_T(bl[nf2][0], bl[nf2][1], bl[nf2][2], bl[nf2][3], wLoA + bo);
        }
        #pragma unroll
        for (int mf = 0; mf < 2; mf++)
            #pragma unroll
            for (int nf = 0; nf < NFR; nf++) {
                uint32_t* bhf = &bh[nf>>1][(nf&1)*2];
                uint32_t* blf = &bl[nf>>1][(nf&1)*2];
                MMA16816(acc[mf][nf], ah[mf], bhf);
                MMA16816(acc[mf][nf], ah[mf], blf);
                MMA16816(acc[mf][nf], al[mf], bhf);
            }
    }
}

template<int NFR>
__device__ __forceinline__ void init_bias(float acc[2][NFR][4],
    const float* __restrict__ b, int lane, int wn)
{
    #pragma unroll
    for (int nf = 0; nf < NFR; nf++) {
        int c = wn*NFR*8 + nf*8 + (lane & 3)*2;
        float b0 = b[c], b1 = b[c + 1];
        #pragma unroll
        for (int mf = 0; mf < 2; mf++) {
            acc[mf][nf][0] = b0; acc[mf][nf][1] = b1;
            acc[mf][nf][2] = b0; acc[mf][nf][3] = b1;
        }
    }
}

template<int NFR>
__device__ __forceinline__ void epi_relu_split(float acc[2][NFR][4],
    __nv_bfloat16* dHi, __nv_bfloat16* dLo, int ldt, int lane, int wn)
{
    #pragma unroll
    for (int mf = 0; mf < 2; mf++) {
        int r0 = mf*16 + (lane >> 2);
        #pragma unroll
        for (int nf = 0; nf < NFR; nf++) {
            int c = wn*NFR*8 + nf*8 + (lane & 3)*2;
            uint32_t hi, lo;
            split2(fmaxf(acc[mf][nf][0], 0.f), fmaxf(acc[mf][nf][1], 0.f), hi, lo);
            *(uint32_t*)&dHi[r0*ldt + c] = hi;
            *(uint32_t*)&dLo[r0*ldt + c] = lo;
            split2(fmaxf(acc[mf][nf][2], 0.f), fmaxf(acc[mf][nf][3], 0.f), hi, lo);
            *(uint32_t*)&dHi[(r0 + 8)*ldt + c] = hi;
            *(uint32_t*)&dLo[(r0 + 8)*ldt + c] = lo;
        }
    }
}

// issue-only async copy of a prepped weight layer (hi+lo) into smem; 1 group
__device__ __forceinline__ void weight_issue(int layer,
    uint32_t wHiA, uint32_t wLoA, int t)
{
    const uint8_t* srcH = (const uint8_t*)pw_hi[layer];
    const uint8_t* srcL = (const uint8_t*)pw_lo[layer];
    for (int idx = t; idx < (64*W_LDT*2)/16; idx += S1_T) {   // 1088
        CP_ASYNC16(wHiA + idx*16, srcH + idx*16);
        CP_ASYNC16(wLoA + idx*16, srcL + idx*16);
    }
    CP_COMMIT();
}

__global__ __launch_bounds__(S1_T) void stage1_kernel(
    const float* __restrict__ x,
    const float* __restrict__ fb1, const float* __restrict__ fb2,
    const float* __restrict__ gb1, const float* __restrict__ gb2,
    float* __restrict__ out)
{
    extern __shared__ __nv_bfloat16 s1[];
    __nv_bfloat16* wAHi = s1;
    __nv_bfloat16* wALo = wAHi + W_PS;
    __nv_bfloat16* wBHi = wALo + W_PS;
    __nv_bfloat16* wBLo = wBHi + W_PS;
    __nv_bfloat16* a0Hi = wBLo + W_PS;
    __nv_bfloat16* a0Lo = a0Hi + A0_PS;
    __nv_bfloat16* a1Hi = a0Lo + A0_PS;
    __nv_bfloat16* a1Lo = a1Hi + A1_PS;

    const int t = threadIdx.x, lane = t & 31, wid = t >> 5;
    const int wn = wid & 3;
    const bool fpath = (blockIdx.x < 512);
    const int nodeBase = (blockIdx.x & 511) * S1_R;

    const uint32_t wAHiA = (uint32_t)__cvta_generic_to_shared(wAHi);
    const uint32_t wALoA = (uint32_t)__cvta_generic_to_shared(wALo);
    const uint32_t wBHiA = (uint32_t)__cvta_generic_to_shared(wBHi);
    const uint32_t wBLoA = (uint32_t)__cvta_generic_to_shared(wBLo);
    const uint32_t a0HiA = (uint32_t)__cvta_generic_to_shared(a0Hi);
    const uint32_t a0LoA = (uint32_t)__cvta_generic_to_shared(a0Lo);
    const uint32_t a1HiA = (uint32_t)__cvta_generic_to_shared(a1Hi);
    const uint32_t a1LoA = (uint32_t)__cvta_generic_to_shared(a1Lo);

    // issue both layer weight loads up-front (groups 0 and 1)
    weight_issue(fpath ? 0 : 2, wAHiA, wALoA, t);
    weight_issue(fpath ? 1 : 3, wBHiA, wBLoA, t);

    // x tile [32 x 64] split (plain LD/ST, overlaps with weight cp.async)
    for (int idx = t; idx < S1_R*64/2; idx += S1_T) {
        int r  = idx >> 5;
        int c2 = (idx & 31) * 2;
        float2 v = *(const float2*)&x[(size_t)(nodeBase + r)*DIN + c2];
        uint32_t hi, lo;
        split2(v.x, v.y, hi, lo);
        *(uint32_t*)&a0Hi[r*A0_LDT + c2] = hi;
        *(uint32_t*)&a0Lo[r*A0_LDT + c2] = lo;
    }

    if (fpath) {
        CP_WAIT1();            // W0 arrived (W1 may pend)
        __syncthreads();
        {   // f1 (wA)
            float acc[2][2][4];
            init_bias<2>(acc, fb1, lane, wn);
            mma_pass<2>(acc, a0HiA, a0LoA, A0_LDT, 0, wAHiA, wALoA, lane, wn);
            epi_relu_split<2>(acc, a1Hi, a1Lo, A1_LDT, lane, wn);
        }
        CP_WAIT0();            // W1 arrived (covered by f1 compute)
        __syncthreads();
        {   // f2 (wB) -> out
            float acc[2][4][4];
            init_bias<4>(acc, fb2, lane, wn);
            mma_pass<4>(acc, a1HiA, a1LoA, A1_LDT, 0, wBHiA, wBLoA, lane, wn);
            #pragma unroll
            for (int mf = 0; mf < 2; mf++) {
                int r0 = nodeBase + mf*16 + (lane >> 2);
                #pragma unroll
                for (int nf = 0; nf < 4; nf++) {
                    int c = wn*32 + nf*8 + (lane & 3)*2;
                    *(float2*)&out[(size_t)r0*DH + c]       = make_float2(acc[mf][nf][0], acc[mf][nf][1]);
                    *(float2*)&out[(size_t)(r0 + 8)*DH + c] = make_float2(acc[mf][nf][2], acc[mf][nf][3]);
                }
            }
        }
    } else {
        CP_WAIT1();            // W2 arrived
        __syncthreads();
        {   // g1 (wA, collapsed g_w1)
            float acc[2][4][4];
            init_bias<4>(acc, gb1, lane, wn);
            mma_pass<4>(acc, a0HiA, a0LoA, A0_LDT, 0, wAHiA, wALoA, lane, wn);
            epi_relu_split<4>(acc, a1Hi, a1Lo, A1_LDT, lane, wn);
        }
        __syncthreads();       // a1 visible; all warps done with wA
        weight_issue(4, wAHiA, wALoA, t);   // W4 -> wA (group 2)

        float acc[2][4][4];
        init_bias<4>(acc, gb2, lane, wn);
        // g2a (wB = g2 rows 0..63); W3 long arrived (groups 0,1 <= wait1)
        CP_WAIT1();
        mma_pass<4>(acc, a1HiA, a1LoA, A1_LDT, 0, wBHiA, wBLoA, lane, wn);
        CP_WAIT0();            // W4 arrived (covered by g2a compute)
        __syncthreads();
        // g2b (wA = g2 rows 64..127)
        mma_pass<4>(acc, a1HiA, a1LoA, A1_LDT, 64, wAHiA, wALoA, lane, wn);

        // epilogue: single fp16 plane -> g_gh [n][i][h] (coalesced)
        #pragma unroll
        for (int mf = 0; mf < 2; mf++) {
            int r0 = nodeBase + mf*16 + (lane >> 2);
            #pragma unroll
            for (int nf = 0; nf < 4; nf++) {
                int c = wn*32 + nf*8 + (lane & 3)*2;
                *(uint32_t*)&g_gh[(size_t)r0*DH + c] =
                    pack_h2(acc[mf][nf][0], acc[mf][nf][1]);
                *(uint32_t*)&g_gh[(size_t)(r0 + 8)*DH + c] =
                    pack_h2(acc[mf][nf][2], acc[mf][nf][3]);
            }
        }
    }
}

// ===========================================================================
// Stage 2 (pure fp16 1-term, 3-stage pipeline):
// out[n,j,h] += sum_i edge[n,i,j]*gx[n,i,h]
// grid (32, 8, KSPLIT=4): BM=64 x BN=128, BK=32.
// G cp.async 2 chunks ahead (wait_group 1); E register-prefetch distance 2.
// Epilogue: atomicAdd into out (RED.ADD, commutative across K-quarters).
// ===========================================================================
#define BK    32
#define EPAD  72
#define GPAD  136
#define SE_PS (BK*EPAD)
#define SG_PS (BK*GPAD)
#define KITER (MM/(BK*KSPLIT))     // 16

__global__ __launch_bounds__(256) void stage2_kernel(
    const float* __restrict__ edge, float* __restrict__ out)
{
    extern __shared__ __half sm2[];
    __half* sE = sm2;                   // [3 buf][BK][EPAD]
    __half* sG = sm2 + 3*SE_PS;         // [3 buf][BK][GPAD]

    const int n  = blockIdx.y;
    const int j0 = blockIdx.x * 64;
    const int kz = blockIdx.z;
    const int koff = kz * (MM / KSPLIT);
    const int t = threadIdx.x, lane = t & 31, wid = t >> 5;
    const int wm = wid >> 2, wn = wid & 3;

    const float* eg = edge + (size_t)n*MM*MM + j0;
    const __half* gh = g_gh + (size_t)n*MM*DH;

    const uint32_t sEb = (uint32_t)__cvta_generic_to_shared(sE);
    const uint32_t sGb = (uint32_t)__cvta_generic_to_shared(sG);

    const int ldrow = t >> 4;          // 0..15 (and +16)
    const int ecol  = (t & 15) * 4;
    const int gcol  = (t & 15) * 8;

    const int arow_off = ((lane >> 4) & 1)*8 + (lane & 7);
    const int aq1      = ((lane >> 3) & 1)*8;
    const int bq       = ((lane >> 4) & 1)*8;

    float acc[2][4][4];
    #pragma unroll
    for (int a = 0; a < 2; a++)
        #pragma unroll
        for (int b = 0; b < 4; b++)
            #pragma unroll
            for (int c = 0; c < 4; c++) acc[a][b][c] = 0.f;

    float4 erA[2], erB[2];

    // ---- prologue ----
    // G chunks 0,1 -> gbuf 0,1 (groups 0,1)
    #pragma unroll
    for (int c = 0; c < 2; c++) {
        #pragma unroll
        for (int u = 0; u < 2; u++) {
            int row = ldrow + u*16;
            CP_ASYNC16(sGb + (uint32_t)((c*BK + row)*GPAD + gcol)*2,
                       gh + (size_t)(koff + c*BK + row)*DH + gcol);
        }
        CP_COMMIT();
    }
    // E chunk 0: LDG -> regs -> STS ebuf0 (one exposed load, prologue only)
    #pragma unroll
    for (int u = 0; u < 2; u++)
        erA[u] = *(const float4*)&eg[(size_t)(koff + ldrow + u*16)*MM + ecol];
    #pragma unroll
    for (int u = 0; u < 2; u++) {
        int row = ldrow + u*16;
        float4 v = erA[u];
        *(uint2*)&sE[(0*BK + row)*EPAD + ecol] =
            make_uint2(pack_h2(v.x, v.y), pack_h2(v.z, v.w));
    }
    // E chunks 1,2 -> regs
    #pragma unroll
    for (int u = 0; u < 2; u++)
        erA[u] = *(const float4*)&eg[(size_t)(koff + 1*BK + ldrow + u*16)*MM + ecol];
    #pragma unroll
    for (int u = 0; u < 2; u++)
        erB[u] = *(const float4*)&eg[(size_t)(koff + 2*BK + ldrow + u*16)*MM + ecol];

    CP_WAIT1();          // G chunk 0 arrived
    __syncthreads();

    for (int kt = 0; kt < KITER; kt++) {
        const int b = kt % 3;

        // 1. G prefetch chunk kt+2 into gbuf (kt+2)%3
        if (kt + 2 < KITER) {
            const int i0 = koff + (kt + 2) * BK;
            const int gb = (kt + 2) % 3;
            #pragma unroll
            for (int u = 0; u < 2; u++) {
                int row = ldrow + u*16;
                CP_ASYNC16(sGb + (uint32_t)((gb*BK + row)*GPAD + gcol)*2,
                           gh + (size_t)(i0 + row)*DH + gcol);
            }
            CP_COMMIT();
        }

        // 2. store E chunk kt+1 (erA) into ebuf (kt+1)%3
        if (kt + 1 < KITER) {
            const int eb = (kt + 1) % 3;
            #pragma unroll
            for (int u = 0; u < 2; u++) {
                int row = ldrow + u*16;
                float4 v = erA[u];
                *(uint2*)&sE[(eb*BK + row)*EPAD + ecol] =
                    make_uint2(pack_h2(v.x, v.y), pack_h2(v.z, v.w));
            }
        }

        // 3. shift regs; LDG E chunk kt+3 into erB (distance-2 prefetch)
        erA[0] = erB[0]; erA[1] = erB[1];
        if (kt + 3 < KITER) {
            const int i0 = koff + (kt + 3) * BK;
            #pragma unroll
            for (int u = 0; u < 2; u++)
                erB[u] = *(const float4*)&eg[(size_t)(i0 + ldrow + u*16)*MM + ecol];
        }

        // 4. compute on buffer b
        #pragma unroll
        for (int ks = 0; ks < BK; ks += 16) {
            uint32_t ah[2][4];
            #pragma unroll
            for (int mf = 0; mf < 2; mf++) {
                int acol = wm*32 + mf*16 + aq1;
                uint32_t a0 = sEb + (uint32_t)(((b*BK + ks + arow_off)*EPAD + acol)*2);
                LDSM_X4_T(ah[mf][0], ah[mf][1], ah[mf][2], ah[mf][3], a0);
            }
            uint32_t bh[2][4];
            #pragma unroll
            for (int nf2 = 0; nf2 < 2; nf2++) {
                int bcol = wn*32 + nf2*16 + bq;
                uint32_t b0 = sGb + (uint32_t)(((b*BK + ks + (lane & 15))*GPAD + bcol)*2);
                LDSM_X4_T(bh[nf2][0], bh[nf2][1], bh[nf2][2], bh[nf2][3], b0);
            }
            #pragma unroll
            for (int mf = 0; mf < 2; mf++)
                #pragma unroll
                for (int nf = 0; nf < 4; nf++) {
                    uint32_t* bhf = &bh[nf>>1][(nf&1)*2];
                    MMAF16(acc[mf][nf], ah[mf], bhf);
                }
        }

        // 5. G chunk kt+1 must have arrived (kt+2 group may pend)
        CP_WAIT1();
        __syncthreads();
    }

    // epilogue: atomic add into out (commutative across K-quarters)
    #pragma unroll
    for (int mf = 0; mf < 2; mf++) {
        int r0 = j0 + wm*32 + mf*16 + (lane >> 2);
        #pragma unroll
        for (int nf = 0; nf < 4; nf++) {
            int c = wn*32 + nf*8 + (lane & 3)*2;
            size_t o0 = ((size_t)n*MM + r0)*DH + c;
            size_t o1 = o0 + (size_t)8*DH;
            atomicAdd(&out[o0],     acc[mf][nf][0]);
            atomicAdd(&out[o0 + 1], acc[mf][nf][1]);
            atomicAdd(&out[o1],     acc[mf][nf][2]);
            atomicAdd(&out[o1 + 1], acc[mf][nf][3]);
        }
    }
}

// ---------------------------------------------------------------------------
extern "C" void kernel_launch(void* const* d_in, const int* in_sizes, int n_in,
                              void* d_out, int out_size)
{
    const float* x    = (const float*)d_in[0];
    const float* edge = (const float*)d_in[1];
    const float* fw1  = (const float*)d_in[2];
    const float* fb1  = (const float*)d_in[3];
    const float* fw2  = (const float*)d_in[4];
    const float* fb2  = (const float*)d_in[5];
    const float* gw1  = (const float*)d_in[6];
    const float* gb1  = (const float*)d_in[7];
    const float* gw2  = (const float*)d_in[8];
    const float* gb2  = (const float*)d_in[9];
    float* out = (float*)d_out;

    const int SMEM1 = (4*W_PS + 2*A0_PS + 2*A1_PS) * 2;   // 96256 B
    const int SMEM2 = (3*SE_PS + 3*SG_PS) * 2;            // 39936 B

    cudaFuncSetAttribute(stage1_kernel, cudaFuncAttributeMaxDynamicSharedMemorySize, SMEM1);
    cudaFuncSetAttribute(stage2_kernel, cudaFuncAttributeMaxDynamicSharedMemorySize, SMEM2);

    prep_kernel<<<72, 256>>>(fw1, fw2, gw1, gw2);
    stage1_kernel<<<1024, S1_T, SMEM1>>>(x, fb1, fb2, gb1, gb2, out);
    stage2_kernel<<<dim3(32, NB, KSPLIT), 256, SMEM2>>>(edge, out);
}